// round 4
// baseline (speedup 1.0000x reference)
#include <cuda_runtime.h>

#define TT 10
#define BB 4
#define CCH 256
#define NPIX 256
#define HIDN 1024
#define TRJ 40
#define EPSF 1e-5f

// ---------------- scratch (device globals; no runtime allocation) ----------------
__device__ float g_A [TT*BB*CCH*NPIX];     // branch gemm+bn out   (t,b,c,n)
__device__ float g_U [BB*TRJ*CCH*NPIX];    // up-conv + bn1 out    (b,j,c,n)
__device__ float g_S1[BB*TRJ*CCH*NPIX];    // lif1 spikes          (b,j,c,n)
__device__ float g_D [BB*TT*CCH*NPIX];     // down-conv + bn2 out  (b,t,c,n)
__device__ float g_Q [TT*BB*CCH*NPIX];     // q spikes             (t,b,c,n)
__device__ float g_K [TT*BB*CCH*NPIX];
__device__ float g_V [TT*BB*CCH*NPIX];
__device__ float g_O [TT*BB*CCH*NPIX];     // attention out (scaled)
__device__ float g_SpO[TT*BB*CCH*NPIX];    // attn_lif spikes
__device__ float g_P [TT*BB*CCH*NPIX];     // proj gemm+bn
__device__ float g_Ss[TT*BB*CCH*NPIX];     // ssa spikes
__device__ float g_H [TT*BB*CCH*NPIX];     // residual h = x + ssa
__device__ float g_F1[TT*BB*HIDN*NPIX];    // fc1 out
__device__ float g_S2[TT*BB*HIDN*NPIX];    // fc1 spikes
__device__ float g_F2[TT*BB*CCH*NPIX];     // fc2 out
__device__ float g_WupT[270*40];           // transposed up-conv weights (tap-major, j contiguous)
__device__ float g_bn1s[40], g_bn1o[40];

// ---------------- prep: transpose up-conv weights, fold bn1 ----------------
__global__ void prep_kernel(const float* __restrict__ up_w, const float* __restrict__ bn1) {
    for (int idx = blockIdx.x*blockDim.x + threadIdx.x; idx < 10800;
         idx += gridDim.x*blockDim.x) {
        int j = idx / 270, r = idx % 270;
        g_WupT[r*40 + j] = up_w[idx];
    }
    int i = blockIdx.x*blockDim.x + threadIdx.x;
    if (i < 40) {
        float gm = bn1[i], bt = bn1[40+i], mu = bn1[80+i], vr = bn1[120+i];
        float s = gm * rsqrtf(vr + EPSF);
        g_bn1s[i] = s; g_bn1o[i] = bt - mu*s;
    }
}

// ---------------- batched GEMM + BN (+bias): Y[g,o,n] = bn(W[o,:]@X[g,:,n] + bias) ----------
// X: [g][CIN][256], W: [Cout][CIN], bnp: [4][Cout]. 64x64 tile, BK=16, 256 thr, 4x4/thread.
template<int CIN>
__global__ void gemm_bn_kernel(const float* __restrict__ X, const float* __restrict__ W,
                               const float* __restrict__ bnp, const float* __restrict__ bias,
                               float* __restrict__ Y, int Cout) {
    const int g = blockIdx.z, mo = blockIdx.y*64, no = blockIdx.x*64;
    __shared__ float Ws[16][64];   // [k][m]
    __shared__ float Xs[16][64];   // [k][n]
    const int tid = threadIdx.x;
    const int tx = tid & 15, ty = tid >> 4;
    float acc[4][4] = {};
    const float* Xg = X + (size_t)g*CIN*256;
    for (int k0 = 0; k0 < CIN; k0 += 16) {
        {   // W tile: thread -> (m = tid/4, kq = (tid%4)*4), float4 over k
            int m = tid >> 2, kq = (tid & 3)*4;
            float4 w4 = *reinterpret_cast<const float4*>(&W[(mo+m)*CIN + k0 + kq]);
            Ws[kq+0][m] = w4.x; Ws[kq+1][m] = w4.y; Ws[kq+2][m] = w4.z; Ws[kq+3][m] = w4.w;
        }
        {   // X tile: thread -> (k = tid/16, nq = (tid%16)*4)
            int k = tid >> 4, nq = (tid & 15)*4;
            float4 x4 = *reinterpret_cast<const float4*>(&Xg[(k0+k)*256 + no + nq]);
            *reinterpret_cast<float4*>(&Xs[k][nq]) = x4;
        }
        __syncthreads();
        #pragma unroll
        for (int kk = 0; kk < 16; kk++) {
            float a[4], bv[4];
            #pragma unroll
            for (int i = 0; i < 4; i++) a[i]  = Ws[kk][ty*4+i];
            #pragma unroll
            for (int j = 0; j < 4; j++) bv[j] = Xs[kk][tx*4+j];
            #pragma unroll
            for (int i = 0; i < 4; i++)
                #pragma unroll
                for (int j = 0; j < 4; j++)
                    acc[i][j] += a[i]*bv[j];
        }
        __syncthreads();
    }
    #pragma unroll
    for (int i = 0; i < 4; i++) {
        int o = mo + ty*4 + i;
        float gm = bnp[o], bt = bnp[Cout+o], mu = bnp[2*Cout+o], vr = bnp[3*Cout+o];
        float s = gm * rsqrtf(vr + EPSF);
        float off = bt - mu*s;
        float bi = bias ? bias[o] : 0.f;
        float4 r;
        r.x = s*(acc[i][0]+bi)+off; r.y = s*(acc[i][1]+bi)+off;
        r.z = s*(acc[i][2]+bi)+off; r.w = s*(acc[i][3]+bi)+off;
        *reinterpret_cast<float4*>(&Y[((size_t)g*Cout + o)*256 + no + tx*4]) = r;
    }
}

// ---------------- TIM up-conv (T=10 in-ch -> 40 out-ch, 3x3x3 over (c,h,w)) + bn1 ---------
// grid (c=256, b=4), 256 threads = one (h,w) pixel each. Input A (t,b,c,n).
__global__ void upconv_kernel(const float* __restrict__ A, float* __restrict__ U) {
    const int c = blockIdx.x, b = blockIdx.y;
    __shared__ float As[9720];   // [t=10][dc=3][hh=18][ww=18]
    const int tid = threadIdx.x;
    for (int idx = tid; idx < 9720; idx += 256) {
        int t = idx / 972, q = idx % 972;
        int dc = q / 324, q2 = q % 324;
        int hh = q2 / 18, ww = q2 % 18;
        int cc = c - 1 + dc;
        float v = 0.f;
        if (cc >= 0 && cc < 256 && hh >= 1 && hh <= 16 && ww >= 1 && ww <= 16)
            v = A[((t*4 + b)*256 + cc)*256 + (hh-1)*16 + (ww-1)];
        As[idx] = v;
    }
    __syncthreads();
    const int h = tid >> 4, w = tid & 15;
    float acc[40];
    #pragma unroll
    for (int j = 0; j < 40; j++) acc[j] = 0.f;
    for (int t = 0; t < 10; t++) {
        #pragma unroll
        for (int dc = 0; dc < 3; dc++)
        #pragma unroll
        for (int dh = 0; dh < 3; dh++)
        #pragma unroll
        for (int dw = 0; dw < 3; dw++) {
            float a = As[t*972 + dc*324 + (h+dh)*18 + (w+dw)];
            const float4* wp =
                reinterpret_cast<const float4*>(&g_WupT[(t*27 + dc*9 + dh*3 + dw)*40]);
            #pragma unroll
            for (int j4 = 0; j4 < 10; j4++) {
                float4 wv = __ldg(&wp[j4]);
                acc[j4*4+0] += wv.x * a;
                acc[j4*4+1] += wv.y * a;
                acc[j4*4+2] += wv.z * a;
                acc[j4*4+3] += wv.w * a;
            }
        }
    }
    #pragma unroll
    for (int j = 0; j < 40; j++)
        U[((b*40 + j)*256 + c)*256 + tid] = g_bn1s[j]*acc[j] + g_bn1o[j];
}

// ---------------- LIF #1 inside TIM: scan over s, chunked (10, 16, C,H,W) ---------------
__global__ void lif_tim1_kernel(const float* __restrict__ U, float* __restrict__ S1) {
    int idx = blockIdx.x*256 + threadIdx.x;      // 16 * 65536 threads
    int inner = idx >> 16, cn = idx & 65535;
    int jr = inner >> 2, b = inner & 3;
    float mem = 0.f;
    #pragma unroll
    for (int s = 0; s < 10; s++) {
        int j = 4*s + jr;
        float x = U[(b*40 + j)*65536 + cn];
        mem += 0.5f*(x - mem);
        float sp = mem > 1.0f ? 1.f : 0.f;
        S1[(b*40 + j)*65536 + cn] = sp;
        if (sp > 0.f) mem = 0.f;
    }
}

// ---------------- TIM down-conv (grouped: out ch t uses in ch [4t,4t+4)) + bn2 -----------
// grid (c=256, b=4, t=10), 256 threads.
__global__ void downconv_kernel(const float* __restrict__ S1, const float* __restrict__ Wd_g,
                                const float* __restrict__ bn2, float* __restrict__ D) {
    const int c = blockIdx.x, b = blockIdx.y, t = blockIdx.z;
    __shared__ float Ss[3888];   // [r=4][dc=3][18][18]
    __shared__ float Wd[108];
    __shared__ float s_sc, s_of;
    const int tid = threadIdx.x;
    if (tid < 108) Wd[tid] = Wd_g[t*108 + tid];
    if (tid == 0) {
        float gm = bn2[t], bt = bn2[10+t], mu = bn2[20+t], vr = bn2[30+t];
        float s = gm * rsqrtf(vr + EPSF);
        s_sc = s; s_of = bt - mu*s;
    }
    for (int idx = tid; idx < 3888; idx += 256) {
        int r = idx / 972, q = idx % 972;
        int dc = q / 324, q2 = q % 324;
        int hh = q2 / 18, ww = q2 % 18;
        int cc = c - 1 + dc;
        float v = 0.f;
        if (cc >= 0 && cc < 256 && hh >= 1 && hh <= 16 && ww >= 1 && ww <= 16)
            v = S1[((b*40 + 4*t + r)*256 + cc)*256 + (hh-1)*16 + (ww-1)];
        Ss[idx] = v;
    }
    __syncthreads();
    const int h = tid >> 4, w = tid & 15;
    float acc = 0.f;
    #pragma unroll
    for (int r = 0; r < 4; r++)
        #pragma unroll
        for (int dc = 0; dc < 3; dc++)
        #pragma unroll
        for (int dh = 0; dh < 3; dh++)
        #pragma unroll
        for (int dw = 0; dw < 3; dw++)
            acc += Wd[r*27 + dc*9 + dh*3 + dw] * Ss[r*972 + dc*324 + (h+dh)*18 + (w+dw)];
    D[(b*10 + t)*65536 + c*256 + tid] = s_sc*acc + s_of;
}

// ---------------- LIF #2 inside TIM: scan over t, (b,t,c,n) -> spikes (t,b,c,n) ----------
__global__ void lif_tim2_kernel(const float* __restrict__ D, float* __restrict__ Out) {
    int idx = blockIdx.x*256 + threadIdx.x;      // 4 * 65536 threads
    int b = idx >> 16, cn = idx & 65535;
    float mem = 0.f;
    #pragma unroll
    for (int t = 0; t < 10; t++) {
        float x = D[(b*10 + t)*65536 + cn];
        mem += 0.5f*(x - mem);
        float sp = mem > 1.0f ? 1.f : 0.f;
        Out[(t*4 + b)*65536 + cn] = sp;
        if (sp > 0.f) mem = 0.f;
    }
}

// ---------------- attention: per (t,b,head), O = (Q K^T) V * 0.25 (no softmax) -----------
// grid (head=16, b=4, t=10), 256 threads = one query row n each.
__global__ void attn_kernel(const float* __restrict__ Qp, const float* __restrict__ Kp,
                            const float* __restrict__ Vp, float* __restrict__ Op) {
    const int hh = blockIdx.x, b = blockIdx.y, t = blockIdx.z;
    __shared__ float Ks[256*20];   // padded row stride 20 (16B aligned)
    __shared__ float Vs[256*20];
    const int base = (t*4 + b)*65536 + hh*16*256;
    const int tid = threadIdx.x;
    for (int idx = tid; idx < 4096; idx += 256) {
        int dd = idx >> 8, m = idx & 255;
        Ks[m*20 + dd] = Kp[base + dd*256 + m];
        Vs[m*20 + dd] = Vp[base + dd*256 + m];
    }
    __syncthreads();
    const int n = tid;
    float q[16];
    #pragma unroll
    for (int dd = 0; dd < 16; dd++) q[dd] = Qp[base + dd*256 + n];
    float acc[16];
    #pragma unroll
    for (int dd = 0; dd < 16; dd++) acc[dd] = 0.f;
    for (int m = 0; m < 256; m++) {
        float s = 0.f;
        #pragma unroll
        for (int qd = 0; qd < 4; qd++) {
            float4 k4 = *reinterpret_cast<const float4*>(&Ks[m*20 + qd*4]);
            s += q[qd*4+0]*k4.x + q[qd*4+1]*k4.y + q[qd*4+2]*k4.z + q[qd*4+3]*k4.w;
        }
        #pragma unroll
        for (int qd = 0; qd < 4; qd++) {
            float4 v4 = *reinterpret_cast<const float4*>(&Vs[m*20 + qd*4]);
            acc[qd*4+0] += s*v4.x; acc[qd*4+1] += s*v4.y;
            acc[qd*4+2] += s*v4.z; acc[qd*4+3] += s*v4.w;
        }
    }
    #pragma unroll
    for (int dd = 0; dd < 16; dd++)
        Op[base + dd*256 + n] = 0.25f*acc[dd];
}

// ---------------- standard LIF over leading T dim, layout (t,b,C,n); optional residual ----
__global__ void lif_std_kernel(const float* __restrict__ in, float* __restrict__ out,
                               const float* __restrict__ res, int Cch, float vth) {
    int idx = blockIdx.x*256 + threadIdx.x;      // 4 * Cch * 256 threads
    int per_b = Cch*256;
    int b = idx / per_b, cn = idx - b*per_b;
    float mem = 0.f;
    #pragma unroll
    for (int t = 0; t < 10; t++) {
        int off = (t*4 + b)*per_b + cn;
        float x = in[off];
        mem += 0.5f*(x - mem);
        float sp = mem > vth ? 1.f : 0.f;
        out[off] = res ? res[off] + sp : sp;
        if (sp > 0.f) mem = 0.f;
    }
}

__global__ void add_kernel(const float* __restrict__ a, const float* __restrict__ b,
                           float* __restrict__ o, int n) {
    int i = blockIdx.x*256 + threadIdx.x;
    if (i < n) o[i] = a[i] + b[i];
}

// ---------------- launch ----------------
extern "C" void kernel_launch(void* const* d_in, const int* in_sizes, int n_in,
                              void* d_out, int out_size) {
    const float* x        = (const float*)d_in[0];
    const float* q_w      = (const float*)d_in[1];
    const float* q_bn     = (const float*)d_in[2];
    const float* k_w      = (const float*)d_in[3];
    const float* k_bn     = (const float*)d_in[4];
    const float* v_w      = (const float*)d_in[5];
    const float* v_bn     = (const float*)d_in[6];
    const float* proj_w   = (const float*)d_in[7];
    const float* proj_bn  = (const float*)d_in[8];
    const float* tim_up_w = (const float*)d_in[9];
    const float* tim_bn1  = (const float*)d_in[10];
    const float* tim_dn_w = (const float*)d_in[11];
    const float* tim_bn2  = (const float*)d_in[12];
    const float* fc1_w    = (const float*)d_in[13];
    const float* fc1_b    = (const float*)d_in[14];
    const float* fc1_bn   = (const float*)d_in[15];
    const float* fc2_w    = (const float*)d_in[16];
    const float* fc2_b    = (const float*)d_in[17];
    const float* fc2_bn   = (const float*)d_in[18];
    float* out = (float*)d_out;

    float *bA,*bU,*bS1,*bD,*bQ,*bK,*bV,*bO,*bSpO,*bP,*bSs,*bH,*bF1,*bS2,*bF2;
    cudaGetSymbolAddress((void**)&bA,  g_A);
    cudaGetSymbolAddress((void**)&bU,  g_U);
    cudaGetSymbolAddress((void**)&bS1, g_S1);
    cudaGetSymbolAddress((void**)&bD,  g_D);
    cudaGetSymbolAddress((void**)&bQ,  g_Q);
    cudaGetSymbolAddress((void**)&bK,  g_K);
    cudaGetSymbolAddress((void**)&bV,  g_V);
    cudaGetSymbolAddress((void**)&bO,  g_O);
    cudaGetSymbolAddress((void**)&bSpO,g_SpO);
    cudaGetSymbolAddress((void**)&bP,  g_P);
    cudaGetSymbolAddress((void**)&bSs, g_Ss);
    cudaGetSymbolAddress((void**)&bH,  g_H);
    cudaGetSymbolAddress((void**)&bF1, g_F1);
    cudaGetSymbolAddress((void**)&bS2, g_S2);
    cudaGetSymbolAddress((void**)&bF2, g_F2);

    prep_kernel<<<43, 256>>>(tim_up_w, tim_bn1);

    const float* ws[3]  = {q_w, k_w, v_w};
    const float* bns[3] = {q_bn, k_bn, v_bn};
    float* dst[3] = {bQ, bK, bV};
    for (int br = 0; br < 3; br++) {
        gemm_bn_kernel<256><<<dim3(4,4,40), 256>>>(x, ws[br], bns[br], nullptr, bA, 256);
        upconv_kernel<<<dim3(256,4), 256>>>(bA, bU);
        lif_tim1_kernel<<<4096, 256>>>(bU, bS1);
        downconv_kernel<<<dim3(256,4,10), 256>>>(bS1, tim_dn_w, tim_bn2, bD);
        lif_tim2_kernel<<<1024, 256>>>(bD, dst[br]);
    }

    attn_kernel<<<dim3(16,4,10), 256>>>(bQ, bK, bV, bO);
    lif_std_kernel<<<1024, 256>>>(bO, bSpO, nullptr, 256, 0.5f);
    gemm_bn_kernel<256><<<dim3(4,4,40), 256>>>(bSpO, proj_w, proj_bn, nullptr, bP, 256);
    lif_std_kernel<<<1024, 256>>>(bP, bSs, nullptr, 256, 1.0f);
    add_kernel<<<10240, 256>>>(x, bSs, bH, TT*BB*CCH*NPIX);

    gemm_bn_kernel<256><<<dim3(4,16,40), 256>>>(bH, fc1_w, fc1_bn, fc1_b, bF1, 1024);
    lif_std_kernel<<<4096, 256>>>(bF1, bS2, nullptr, 1024, 1.0f);
    gemm_bn_kernel<1024><<<dim3(4,4,40), 256>>>(bS2, fc2_w, fc2_bn, fc2_b, bF2, 256);
    lif_std_kernel<<<1024, 256>>>(bF2, out, bH, 256, 1.0f);
}

// round 5
// speedup vs baseline: 1.3774x; 1.3774x over previous
#include <cuda_runtime.h>

#define TT 10
#define BB 4
#define CCH 256
#define NPIX 256
#define HIDN 1024
#define TRJ 40
#define EPSF 1e-5f

typedef unsigned long long u64;

// f32x2 packed-math helpers (sm_103a)
#define FMA2(d,a,b)    asm("fma.rn.f32x2 %0, %1, %2, %0;" : "+l"(d) : "l"(a), "l"(b))
#define FMA2N(d,a,b,c) asm("fma.rn.f32x2 %0, %1, %2, %3;" : "=l"(d) : "l"(a), "l"(b), "l"(c))
#define PACK2(d,lo,hi) asm("mov.b64 %0, {%1, %2};" : "=l"(d) : "f"(lo), "f"(hi))
#define UNPACK2(lo,hi,s) asm("mov.b64 {%0, %1}, %2;" : "=f"(lo), "=f"(hi) : "l"(s))

#define BR_STRIDE_A  2621440     // 10*4*256*256
#define BR_STRIDE_U  10485760    // 4*40*256*256

// ---------------- scratch (device globals; no runtime allocation) ----------------
__device__ float g_A  [3*TT*BB*CCH*NPIX];   // branch gemm+bn out   (br,t,b,c,n)
__device__ float g_U  [3*BB*TRJ*CCH*NPIX];  // up-conv + bn1 out    (br,b,j,c,n)
__device__ float g_S1 [3*BB*TRJ*CCH*NPIX];  // lif1 spikes
__device__ float g_D  [3*BB*TT*CCH*NPIX];   // down-conv + bn2 out  (br,b,t,c,n)
__device__ float g_QKV[3*TT*BB*CCH*NPIX];   // q/k/v spikes         (br,t,b,c,n)
__device__ float g_O  [TT*BB*CCH*NPIX];     // attention out
__device__ float g_SpO[TT*BB*CCH*NPIX];     // attn_lif spikes
__device__ float g_P  [TT*BB*CCH*NPIX];     // proj gemm+bn
__device__ float g_H  [TT*BB*CCH*NPIX];     // residual h = x + ssa
__device__ float g_F1 [TT*BB*HIDN*NPIX];    // fc1 out
__device__ float g_S2 [TT*BB*HIDN*NPIX];    // fc1 spikes
__device__ float g_F2 [TT*BB*CCH*NPIX];     // fc2 out
__device__ float g_WupT[270*40];            // transposed up-conv weights (tap-major, j contiguous)
__device__ float g_bn1s[40], g_bn1o[40];

// ---------------- prep: transpose up-conv weights, fold bn1 ----------------
__global__ void prep_kernel(const float* __restrict__ up_w, const float* __restrict__ bn1) {
    for (int idx = blockIdx.x*blockDim.x + threadIdx.x; idx < 10800;
         idx += gridDim.x*blockDim.x) {
        int j = idx / 270, r = idx % 270;
        g_WupT[r*40 + j] = up_w[idx];
    }
    int i = blockIdx.x*blockDim.x + threadIdx.x;
    if (i < 40) {
        float gm = bn1[i], bt = bn1[40+i], mu = bn1[80+i], vr = bn1[120+i];
        float s = gm * rsqrtf(vr + EPSF);
        g_bn1s[i] = s; g_bn1o[i] = bt - mu*s;
    }
}

// ---------------- batched GEMM + BN (+bias), f32x2 accumulation -----------------
// Y[br,g,o,n] = bn(W_br[o,:] @ X[g,:,n] + bias). 64(m)x128(n) tile, BK=16, 256 thr,
// 4m x 8n (4 f32x2) per thread. grid (2, Cout/64, nbr*40).
template<int CIN>
__global__ void gemm_bn_kernel(const float* __restrict__ X,
        const float* __restrict__ W0, const float* __restrict__ W1, const float* __restrict__ W2,
        const float* __restrict__ B0, const float* __restrict__ B1, const float* __restrict__ B2,
        const float* __restrict__ bias, float* __restrict__ Y, int Cout) {
    const int zz = blockIdx.z;
    const int br = zz / 40, g = zz - br*40;
    const float* W   = (br == 0) ? W0 : ((br == 1) ? W1 : W2);
    const float* bnp = (br == 0) ? B0 : ((br == 1) ? B1 : B2);
    float* Yb = Y + (size_t)br * 40 * Cout * 256;
    const int mo = blockIdx.y*64, no = blockIdx.x*128;
    __shared__ __align__(16) float Ws[16][64];
    __shared__ __align__(16) float Xs[16][128];
    const int tid = threadIdx.x;
    const int tx = tid & 15, ty = tid >> 4;
    u64 acc[4][4];
    #pragma unroll
    for (int i = 0; i < 4; i++)
        #pragma unroll
        for (int j = 0; j < 4; j++) acc[i][j] = 0ull;
    const float* Xg = X + (size_t)g*CIN*256;
    for (int k0 = 0; k0 < CIN; k0 += 16) {
        {   // W tile 64x16
            int m = tid >> 2, kq = (tid & 3)*4;
            float4 w4 = *reinterpret_cast<const float4*>(&W[(mo+m)*CIN + k0 + kq]);
            Ws[kq+0][m] = w4.x; Ws[kq+1][m] = w4.y; Ws[kq+2][m] = w4.z; Ws[kq+3][m] = w4.w;
        }
        {   // X tile 16x128
            int kr = tid >> 4, nq = (tid & 15)*8;
            *reinterpret_cast<float4*>(&Xs[kr][nq]) =
                *reinterpret_cast<const float4*>(&Xg[(k0+kr)*256 + no + nq]);
            *reinterpret_cast<float4*>(&Xs[kr][nq+4]) =
                *reinterpret_cast<const float4*>(&Xg[(k0+kr)*256 + no + nq + 4]);
        }
        __syncthreads();
        #pragma unroll
        for (int kk = 0; kk < 16; kk++) {
            u64 a2[4];
            #pragma unroll
            for (int i = 0; i < 4; i++) { float a = Ws[kk][ty*4+i]; PACK2(a2[i], a, a); }
            ulonglong2 bb0 = *reinterpret_cast<const ulonglong2*>(&Xs[kk][tx*8]);
            ulonglong2 bb1 = *reinterpret_cast<const ulonglong2*>(&Xs[kk][tx*8+4]);
            u64 b2[4] = {bb0.x, bb0.y, bb1.x, bb1.y};
            #pragma unroll
            for (int i = 0; i < 4; i++)
                #pragma unroll
                for (int j = 0; j < 4; j++)
                    FMA2(acc[i][j], a2[i], b2[j]);
        }
        __syncthreads();
    }
    #pragma unroll
    for (int i = 0; i < 4; i++) {
        int o = mo + ty*4 + i;
        float gm = bnp[o], bt = bnp[Cout+o], mu = bnp[2*Cout+o], vr = bnp[3*Cout+o];
        float s = gm * rsqrtf(vr + EPSF);
        float off = bt - mu*s + (bias ? s*bias[o] : 0.f);
        u64 s2, o2; PACK2(s2, s, s); PACK2(o2, off, off);
        float r[8];
        #pragma unroll
        for (int j = 0; j < 4; j++) {
            u64 d; FMA2N(d, acc[i][j], s2, o2);
            UNPACK2(r[2*j], r[2*j+1], d);
        }
        float* yp = &Yb[((size_t)g*Cout + o)*256 + no + tx*8];
        *reinterpret_cast<float4*>(yp)   = make_float4(r[0], r[1], r[2], r[3]);
        *reinterpret_cast<float4*>(yp+4) = make_float4(r[4], r[5], r[6], r[7]);
    }
}

// ---------------- TIM up-conv (10 in-ch -> 40 out-ch, 3x3x3 over (c,h,w)) + bn1 ---------
// grid (c=256, b=4, br=3), 256 threads = one (h,w) pixel each. Weights cached in smem,
// f32x2 accumulation across output-channel pairs. Dynamic smem = 82080 B.
__global__ void upconv_kernel(const float* __restrict__ A, float* __restrict__ U) {
    extern __shared__ float sm[];
    float* As  = sm;          // [10][3][18][18] = 9720
    float* Wsm = sm + 9720;   // [270][40]       = 10800
    const int c = blockIdx.x, b = blockIdx.y, br = blockIdx.z;
    const float* Ab = A + (size_t)br * BR_STRIDE_A;
    float* Ub = U + (size_t)br * BR_STRIDE_U;
    const int tid = threadIdx.x;
    for (int i = tid; i < 10800; i += 256) Wsm[i] = g_WupT[i];
    for (int idx = tid; idx < 9720; idx += 256) {
        int t = idx / 972, q = idx % 972;
        int dc = q / 324, q2 = q % 324;
        int hh = q2 / 18, ww = q2 % 18;
        int cc = c - 1 + dc;
        float v = 0.f;
        if (cc >= 0 && cc < 256 && hh >= 1 && hh <= 16 && ww >= 1 && ww <= 16)
            v = Ab[((t*4 + b)*256 + cc)*256 + (hh-1)*16 + (ww-1)];
        As[idx] = v;
    }
    __syncthreads();
    const int h = tid >> 4, w = tid & 15;
    u64 acc[20];
    #pragma unroll
    for (int j = 0; j < 20; j++) acc[j] = 0ull;
    for (int t = 0; t < 10; t++) {
        const float* at = As + t*972 + h*18 + w;
        const u64* wt = reinterpret_cast<const u64*>(Wsm) + t*540;   // 27 taps * 20 pairs
        #pragma unroll
        for (int dc = 0; dc < 3; dc++)
            #pragma unroll
            for (int dh = 0; dh < 3; dh++)
                #pragma unroll
                for (int dw = 0; dw < 3; dw++) {
                    float a = at[dc*324 + dh*18 + dw];
                    u64 a2; PACK2(a2, a, a);
                    const u64* wp = wt + (dc*9 + dh*3 + dw)*20;
                    #pragma unroll
                    for (int j = 0; j < 20; j++) FMA2(acc[j], a2, wp[j]);
                }
    }
    #pragma unroll
    for (int j = 0; j < 20; j++) {
        float lo, hi; UNPACK2(lo, hi, acc[j]);
        int j0 = 2*j;
        Ub[((b*40 + j0  )*256 + c)*256 + tid] = g_bn1s[j0  ]*lo + g_bn1o[j0  ];
        Ub[((b*40 + j0+1)*256 + c)*256 + tid] = g_bn1s[j0+1]*hi + g_bn1o[j0+1];
    }
}

// ---------------- LIF #1 inside TIM: scan over s, chunked (10, 16, C,H,W), 3 branches ----
__global__ void lif_tim1_kernel(const float* __restrict__ U, float* __restrict__ S1) {
    int br = blockIdx.x >> 12;               // 4096 blocks per branch
    int idx = (blockIdx.x & 4095)*256 + threadIdx.x;
    int inner = idx >> 16, cn = idx & 65535;
    int jr = inner >> 2, b = inner & 3;
    const float* Ub = U + (size_t)br * BR_STRIDE_U;
    float* Sb = S1 + (size_t)br * BR_STRIDE_U;
    float mem = 0.f;
    #pragma unroll
    for (int s = 0; s < 10; s++) {
        int j = 4*s + jr;
        float x = Ub[(b*40 + j)*65536 + cn];
        mem += 0.5f*(x - mem);
        float sp = mem > 1.0f ? 1.f : 0.f;
        Sb[(b*40 + j)*65536 + cn] = sp;
        if (sp > 0.f) mem = 0.f;
    }
}

// ---------------- TIM down-conv (grouped) + bn2, 3 branches ------------------------------
// grid (c=256, b=4, br*10+t), 256 threads.
__global__ void downconv_kernel(const float* __restrict__ S1, const float* __restrict__ Wd_g,
                                const float* __restrict__ bn2, float* __restrict__ D) {
    const int c = blockIdx.x, b = blockIdx.y;
    const int br = blockIdx.z / 10, t = blockIdx.z - br*10;
    const float* Sb = S1 + (size_t)br * BR_STRIDE_U;
    float* Db = D + (size_t)br * BR_STRIDE_A;
    __shared__ float Ss[3888];   // [r=4][dc=3][18][18]
    __shared__ float Wd[108];
    __shared__ float s_sc, s_of;
    const int tid = threadIdx.x;
    if (tid < 108) Wd[tid] = Wd_g[t*108 + tid];
    if (tid == 0) {
        float gm = bn2[t], bt = bn2[10+t], mu = bn2[20+t], vr = bn2[30+t];
        float s = gm * rsqrtf(vr + EPSF);
        s_sc = s; s_of = bt - mu*s;
    }
    for (int idx = tid; idx < 3888; idx += 256) {
        int r = idx / 972, q = idx % 972;
        int dc = q / 324, q2 = q % 324;
        int hh = q2 / 18, ww = q2 % 18;
        int cc = c - 1 + dc;
        float v = 0.f;
        if (cc >= 0 && cc < 256 && hh >= 1 && hh <= 16 && ww >= 1 && ww <= 16)
            v = Sb[((b*40 + 4*t + r)*256 + cc)*256 + (hh-1)*16 + (ww-1)];
        Ss[idx] = v;
    }
    __syncthreads();
    const int h = tid >> 4, w = tid & 15;
    float acc = 0.f;
    #pragma unroll
    for (int r = 0; r < 4; r++)
        #pragma unroll
        for (int dc = 0; dc < 3; dc++)
            #pragma unroll
            for (int dh = 0; dh < 3; dh++)
                #pragma unroll
                for (int dw = 0; dw < 3; dw++)
                    acc += Wd[r*27 + dc*9 + dh*3 + dw] * Ss[r*972 + dc*324 + (h+dh)*18 + (w+dw)];
    Db[(b*10 + t)*65536 + c*256 + tid] = s_sc*acc + s_of;
}

// ---------------- LIF #2 inside TIM: scan over t, (b,t,c,n) -> spikes (t,b,c,n), 3 br ----
__global__ void lif_tim2_kernel(const float* __restrict__ D, float* __restrict__ Out) {
    int br = blockIdx.x >> 10;               // 1024 blocks per branch
    int idx = (blockIdx.x & 1023)*256 + threadIdx.x;
    int b = idx >> 16, cn = idx & 65535;
    const float* Db = D + (size_t)br * BR_STRIDE_A;
    float* Ob = Out + (size_t)br * BR_STRIDE_A;
    float mem = 0.f;
    #pragma unroll
    for (int t = 0; t < 10; t++) {
        float x = Db[(b*10 + t)*65536 + cn];
        mem += 0.5f*(x - mem);
        float sp = mem > 1.0f ? 1.f : 0.f;
        Ob[(t*4 + b)*65536 + cn] = sp;
        if (sp > 0.f) mem = 0.f;
    }
}

// ---------------- attention: per (t,b,head), O = (Q K^T) V * 0.25, f32x2 ----------------
__global__ void attn_kernel(const float* __restrict__ Qp, const float* __restrict__ Kp,
                            const float* __restrict__ Vp, float* __restrict__ Op) {
    const int hh = blockIdx.x, b = blockIdx.y, t = blockIdx.z;
    __shared__ __align__(16) float Ks[256*20];   // row stride 20 floats (80B, 16B-aligned)
    __shared__ __align__(16) float Vs[256*20];
    const int base = (t*4 + b)*65536 + hh*4096;
    const int tid = threadIdx.x;
    for (int idx = tid; idx < 4096; idx += 256) {
        int dd = idx >> 8, m = idx & 255;
        Ks[m*20 + dd] = Kp[base + dd*256 + m];
        Vs[m*20 + dd] = Vp[base + dd*256 + m];
    }
    __syncthreads();
    const int n = tid;
    float qv[16];
    #pragma unroll
    for (int dd = 0; dd < 16; dd++) qv[dd] = Qp[base + dd*256 + n];
    u64 q2[8];
    #pragma unroll
    for (int i = 0; i < 8; i++) PACK2(q2[i], qv[2*i], qv[2*i+1]);
    u64 acc2[8];
    #pragma unroll
    for (int i = 0; i < 8; i++) acc2[i] = 0ull;
    for (int m = 0; m < 256; m++) {
        const u64* kp = reinterpret_cast<const u64*>(&Ks[m*20]);
        u64 sa = 0ull, sb = 0ull;     // two independent f32x2 partial chains
        #pragma unroll
        for (int i = 0; i < 4; i++) { FMA2(sa, q2[2*i], kp[2*i]); FMA2(sb, q2[2*i+1], kp[2*i+1]); }
        float a0, a1, b0, b1;
        UNPACK2(a0, a1, sa); UNPACK2(b0, b1, sb);
        float s = (a0 + a1) + (b0 + b1);
        u64 ss; PACK2(ss, s, s);
        const u64* vp = reinterpret_cast<const u64*>(&Vs[m*20]);
        #pragma unroll
        for (int i = 0; i < 8; i++) FMA2(acc2[i], ss, vp[i]);
    }
    #pragma unroll
    for (int i = 0; i < 8; i++) {
        float lo, hi; UNPACK2(lo, hi, acc2[i]);
        Op[base + (2*i  )*256 + n] = 0.25f*lo;
        Op[base + (2*i+1)*256 + n] = 0.25f*hi;
    }
}

// ---------------- standard LIF over leading T dim, layout (t,b,C,n); optional residual ----
__global__ void lif_std_kernel(const float* __restrict__ in, float* __restrict__ out,
                               const float* __restrict__ res, int Cch, float vth) {
    int idx = blockIdx.x*256 + threadIdx.x;
    int per_b = Cch*256;
    int b = idx / per_b, cn = idx - b*per_b;
    float mem = 0.f;
    #pragma unroll
    for (int t = 0; t < 10; t++) {
        int off = (t*4 + b)*per_b + cn;
        float x = in[off];
        mem += 0.5f*(x - mem);
        float sp = mem > vth ? 1.f : 0.f;
        out[off] = res ? res[off] + sp : sp;
        if (sp > 0.f) mem = 0.f;
    }
}

// ---------------- launch ----------------
extern "C" void kernel_launch(void* const* d_in, const int* in_sizes, int n_in,
                              void* d_out, int out_size) {
    const float* x        = (const float*)d_in[0];
    const float* q_w      = (const float*)d_in[1];
    const float* q_bn     = (const float*)d_in[2];
    const float* k_w      = (const float*)d_in[3];
    const float* k_bn     = (const float*)d_in[4];
    const float* v_w      = (const float*)d_in[5];
    const float* v_bn     = (const float*)d_in[6];
    const float* proj_w   = (const float*)d_in[7];
    const float* proj_bn  = (const float*)d_in[8];
    const float* tim_up_w = (const float*)d_in[9];
    const float* tim_bn1  = (const float*)d_in[10];
    const float* tim_dn_w = (const float*)d_in[11];
    const float* tim_bn2  = (const float*)d_in[12];
    const float* fc1_w    = (const float*)d_in[13];
    const float* fc1_b    = (const float*)d_in[14];
    const float* fc1_bn   = (const float*)d_in[15];
    const float* fc2_w    = (const float*)d_in[16];
    const float* fc2_b    = (const float*)d_in[17];
    const float* fc2_bn   = (const float*)d_in[18];
    float* out = (float*)d_out;

    float *bA,*bU,*bS1,*bD,*bQKV,*bO,*bSpO,*bP,*bH,*bF1,*bS2,*bF2;
    cudaGetSymbolAddress((void**)&bA,   g_A);
    cudaGetSymbolAddress((void**)&bU,   g_U);
    cudaGetSymbolAddress((void**)&bS1,  g_S1);
    cudaGetSymbolAddress((void**)&bD,   g_D);
    cudaGetSymbolAddress((void**)&bQKV, g_QKV);
    cudaGetSymbolAddress((void**)&bO,   g_O);
    cudaGetSymbolAddress((void**)&bSpO, g_SpO);
    cudaGetSymbolAddress((void**)&bP,   g_P);
    cudaGetSymbolAddress((void**)&bH,   g_H);
    cudaGetSymbolAddress((void**)&bF1,  g_F1);
    cudaGetSymbolAddress((void**)&bS2,  g_S2);
    cudaGetSymbolAddress((void**)&bF2,  g_F2);

    cudaFuncSetAttribute(upconv_kernel, cudaFuncAttributeMaxDynamicSharedMemorySize, 82080);

    prep_kernel<<<43, 256>>>(tim_up_w, tim_bn1);

    // --- q/k/v branches, batched across br at every stage ---
    gemm_bn_kernel<256><<<dim3(2,4,120), 256>>>(x, q_w, k_w, v_w, q_bn, k_bn, v_bn,
                                                nullptr, bA, 256);
    upconv_kernel<<<dim3(256,4,3), 256, 82080>>>(bA, bU);
    lif_tim1_kernel<<<12288, 256>>>(bU, bS1);
    downconv_kernel<<<dim3(256,4,30), 256>>>(bS1, tim_dn_w, tim_bn2, bD);
    lif_tim2_kernel<<<3072, 256>>>(bD, bQKV);

    // --- attention + proj ---
    attn_kernel<<<dim3(16,4,10), 256>>>(bQKV, bQKV + BR_STRIDE_A, bQKV + 2*BR_STRIDE_A, bO);
    lif_std_kernel<<<1024, 256>>>(bO, bSpO, nullptr, 256, 0.5f);
    gemm_bn_kernel<256><<<dim3(2,4,40), 256>>>(bSpO, proj_w, proj_w, proj_w,
                                               proj_bn, proj_bn, proj_bn, nullptr, bP, 256);
    lif_std_kernel<<<1024, 256>>>(bP, bH, x, 256, 1.0f);   // h = x + ssa

    // --- mlp ---
    gemm_bn_kernel<256><<<dim3(2,16,40), 256>>>(bH, fc1_w, fc1_w, fc1_w,
                                                fc1_bn, fc1_bn, fc1_bn, fc1_b, bF1, 1024);
    lif_std_kernel<<<4096, 256>>>(bF1, bS2, nullptr, 1024, 1.0f);
    gemm_bn_kernel<1024><<<dim3(2,4,40), 256>>>(bS2, fc2_w, fc2_w, fc2_w,
                                                fc2_bn, fc2_bn, fc2_bn, fc2_b, bF2, 256);
    lif_std_kernel<<<1024, 256>>>(bF2, out, bH, 256, 1.0f);
}

// round 7
// speedup vs baseline: 1.3776x; 1.0001x over previous
#include <cuda_runtime.h>

#define TT 10
#define BB 4
#define CCH 256
#define NPIX 256
#define HIDN 1024
#define TRJ 40
#define EPSF 1e-5f

typedef unsigned long long u64;

// f32x2 packed-math helpers (sm_103a)
#define FMA2(d,a,b)    asm("fma.rn.f32x2 %0, %1, %2, %0;" : "+l"(d) : "l"(a), "l"(b))
#define FMA2N(d,a,b,c) asm("fma.rn.f32x2 %0, %1, %2, %3;" : "=l"(d) : "l"(a), "l"(b), "l"(c))
#define PACK2(d,lo,hi) asm("mov.b64 %0, {%1, %2};" : "=l"(d) : "f"(lo), "f"(hi))
#define UNPACK2(lo,hi,s) asm("mov.b64 {%0, %1}, %2;" : "=f"(lo), "=f"(hi) : "l"(s))

#define BR_STRIDE_A  2621440     // 10*4*256*256
#define BR_STRIDE_U  10485760    // 4*40*256*256

// ---------------- scratch (device globals; no runtime allocation) ----------------
__device__ float g_A  [3*TT*BB*CCH*NPIX];   // branch gemm+bn out   (br,t,b,c,n)
__device__ float g_S1 [3*BB*TRJ*CCH*NPIX];  // lif1 spikes          (br,b,j,c,n)
__device__ float g_QKV[3*TT*BB*CCH*NPIX];   // q/k/v spikes         (br,t,b,c,n)
__device__ float g_SpO[TT*BB*CCH*NPIX];     // attn_lif spikes
__device__ float g_P  [TT*BB*CCH*NPIX];     // proj gemm+bn
__device__ float g_H  [TT*BB*CCH*NPIX];     // residual h = x + ssa
__device__ float g_S2 [TT*BB*HIDN*NPIX];    // fc1 spikes
__device__ float g_F2 [TT*BB*CCH*NPIX];     // fc2 out
__device__ float g_WupT[270*40];            // transposed up-conv weights (tap-major)
__device__ float g_bn1s[40], g_bn1o[40];

// ---------------- prep: transpose up-conv weights, fold bn1 ----------------
__global__ void prep_kernel(const float* __restrict__ up_w, const float* __restrict__ bn1) {
    for (int idx = blockIdx.x*blockDim.x + threadIdx.x; idx < 10800;
         idx += gridDim.x*blockDim.x) {
        int j = idx / 270, r = idx % 270;
        g_WupT[r*40 + j] = up_w[idx];
    }
    int i = blockIdx.x*blockDim.x + threadIdx.x;
    if (i < 40) {
        float gm = bn1[i], bt = bn1[40+i], mu = bn1[80+i], vr = bn1[120+i];
        float s = gm * rsqrtf(vr + EPSF);
        g_bn1s[i] = s; g_bn1o[i] = bt - mu*s;
    }
}

// ---------------- batched GEMM + BN (+bias), f32x2 accumulation -----------------
// Y[br,g,o,n] = bn(W_br[o,:] @ X[g,:,n] + bias). 64x128 tile, BK=16, 256 thr.
template<int CIN>
__global__ void gemm_bn_kernel(const float* __restrict__ X,
        const float* __restrict__ W0, const float* __restrict__ W1, const float* __restrict__ W2,
        const float* __restrict__ B0, const float* __restrict__ B1, const float* __restrict__ B2,
        const float* __restrict__ bias, float* __restrict__ Y, int Cout) {
    const int zz = blockIdx.z;
    const int br = zz / 40, g = zz - br*40;
    const float* W   = (br == 0) ? W0 : ((br == 1) ? W1 : W2);
    const float* bnp = (br == 0) ? B0 : ((br == 1) ? B1 : B2);
    float* Yb = Y + (size_t)br * 40 * Cout * 256;
    const int mo = blockIdx.y*64, no = blockIdx.x*128;
    __shared__ __align__(16) float Ws[16][64];
    __shared__ __align__(16) float Xs[16][128];
    const int tid = threadIdx.x;
    const int tx = tid & 15, ty = tid >> 4;
    u64 acc[4][4];
    #pragma unroll
    for (int i = 0; i < 4; i++)
        #pragma unroll
        for (int j = 0; j < 4; j++) acc[i][j] = 0ull;
    const float* Xg = X + (size_t)g*CIN*256;
    for (int k0 = 0; k0 < CIN; k0 += 16) {
        {
            int m = tid >> 2, kq = (tid & 3)*4;
            float4 w4 = *reinterpret_cast<const float4*>(&W[(mo+m)*CIN + k0 + kq]);
            Ws[kq+0][m] = w4.x; Ws[kq+1][m] = w4.y; Ws[kq+2][m] = w4.z; Ws[kq+3][m] = w4.w;
        }
        {
            int kr = tid >> 4, nq = (tid & 15)*8;
            *reinterpret_cast<float4*>(&Xs[kr][nq]) =
                *reinterpret_cast<const float4*>(&Xg[(k0+kr)*256 + no + nq]);
            *reinterpret_cast<float4*>(&Xs[kr][nq+4]) =
                *reinterpret_cast<const float4*>(&Xg[(k0+kr)*256 + no + nq + 4]);
        }
        __syncthreads();
        #pragma unroll
        for (int kk = 0; kk < 16; kk++) {
            u64 a2[4];
            #pragma unroll
            for (int i = 0; i < 4; i++) { float a = Ws[kk][ty*4+i]; PACK2(a2[i], a, a); }
            ulonglong2 bb0 = *reinterpret_cast<const ulonglong2*>(&Xs[kk][tx*8]);
            ulonglong2 bb1 = *reinterpret_cast<const ulonglong2*>(&Xs[kk][tx*8+4]);
            u64 b2[4] = {bb0.x, bb0.y, bb1.x, bb1.y};
            #pragma unroll
            for (int i = 0; i < 4; i++)
                #pragma unroll
                for (int j = 0; j < 4; j++)
                    FMA2(acc[i][j], a2[i], b2[j]);
        }
        __syncthreads();
    }
    #pragma unroll
    for (int i = 0; i < 4; i++) {
        int o = mo + ty*4 + i;
        float gm = bnp[o], bt = bnp[Cout+o], mu = bnp[2*Cout+o], vr = bnp[3*Cout+o];
        float s = gm * rsqrtf(vr + EPSF);
        float off = bt - mu*s + (bias ? s*bias[o] : 0.f);
        u64 s2, o2; PACK2(s2, s, s); PACK2(o2, off, off);
        float r[8];
        #pragma unroll
        for (int j = 0; j < 4; j++) {
            u64 d; FMA2N(d, acc[i][j], s2, o2);
            UNPACK2(r[2*j], r[2*j+1], d);
        }
        float* yp = &Yb[((size_t)g*Cout + o)*256 + no + tx*8];
        *reinterpret_cast<float4*>(yp)   = make_float4(r[0], r[1], r[2], r[3]);
        *reinterpret_cast<float4*>(yp+4) = make_float4(r[4], r[5], r[6], r[7]);
    }
}

// ---------------- GEMM + BN + bias + fused LIF over t (used for fc1) --------------------
// grid (nx, Cout/64, b=4); internal t-loop with membrane in registers; writes spikes.
template<int CIN>
__global__ void gemm_lif_kernel(const float* __restrict__ X, const float* __restrict__ W,
                                const float* __restrict__ bnp, const float* __restrict__ bias,
                                float* __restrict__ Y, int Cout) {
    const int b = blockIdx.z;
    const int mo = blockIdx.y*64, no = blockIdx.x*128;
    __shared__ __align__(16) float Ws[16][64];
    __shared__ __align__(16) float Xs[16][128];
    const int tid = threadIdx.x;
    const int tx = tid & 15, ty = tid >> 4;
    float bns[4], bno[4];
    #pragma unroll
    for (int i = 0; i < 4; i++) {
        int o = mo + ty*4 + i;
        float gm = bnp[o], bt = bnp[Cout+o], mu = bnp[2*Cout+o], vr = bnp[3*Cout+o];
        float s = gm * rsqrtf(vr + EPSF);
        bns[i] = s; bno[i] = bt - mu*s + (bias ? s*bias[o] : 0.f);
    }
    float mem[4][8];
    #pragma unroll
    for (int i = 0; i < 4; i++)
        #pragma unroll
        for (int j = 0; j < 8; j++) mem[i][j] = 0.f;

    for (int t = 0; t < 10; t++) {
        const float* Xg = X + ((size_t)(t*4 + b))*CIN*256;
        u64 acc[4][4];
        #pragma unroll
        for (int i = 0; i < 4; i++)
            #pragma unroll
            for (int j = 0; j < 4; j++) acc[i][j] = 0ull;
        for (int k0 = 0; k0 < CIN; k0 += 16) {
            {
                int m = tid >> 2, kq = (tid & 3)*4;
                float4 w4 = *reinterpret_cast<const float4*>(&W[(mo+m)*CIN + k0 + kq]);
                Ws[kq+0][m] = w4.x; Ws[kq+1][m] = w4.y; Ws[kq+2][m] = w4.z; Ws[kq+3][m] = w4.w;
            }
            {
                int kr = tid >> 4, nq = (tid & 15)*8;
                *reinterpret_cast<float4*>(&Xs[kr][nq]) =
                    *reinterpret_cast<const float4*>(&Xg[(k0+kr)*256 + no + nq]);
                *reinterpret_cast<float4*>(&Xs[kr][nq+4]) =
                    *reinterpret_cast<const float4*>(&Xg[(k0+kr)*256 + no + nq + 4]);
            }
            __syncthreads();
            #pragma unroll
            for (int kk = 0; kk < 16; kk++) {
                u64 a2[4];
                #pragma unroll
                for (int i = 0; i < 4; i++) { float a = Ws[kk][ty*4+i]; PACK2(a2[i], a, a); }
                ulonglong2 bb0 = *reinterpret_cast<const ulonglong2*>(&Xs[kk][tx*8]);
                ulonglong2 bb1 = *reinterpret_cast<const ulonglong2*>(&Xs[kk][tx*8+4]);
                u64 b2[4] = {bb0.x, bb0.y, bb1.x, bb1.y};
                #pragma unroll
                for (int i = 0; i < 4; i++)
                    #pragma unroll
                    for (int j = 0; j < 4; j++)
                        FMA2(acc[i][j], a2[i], b2[j]);
            }
            __syncthreads();
        }
        #pragma unroll
        for (int i = 0; i < 4; i++) {
            int o = mo + ty*4 + i;
            float r[8];
            #pragma unroll
            for (int j = 0; j < 4; j++) {
                float lo, hi; UNPACK2(lo, hi, acc[i][j]);
                r[2*j] = bns[i]*lo + bno[i]; r[2*j+1] = bns[i]*hi + bno[i];
            }
            float sp[8];
            #pragma unroll
            for (int j = 0; j < 8; j++) {
                float m2 = mem[i][j] + 0.5f*(r[j] - mem[i][j]);
                float s = m2 > 1.0f ? 1.f : 0.f;
                sp[j] = s;
                mem[i][j] = (s > 0.f) ? 0.f : m2;
            }
            float* yp = &Y[((size_t)(t*4 + b)*Cout + o)*256 + no + tx*8];
            *reinterpret_cast<float4*>(yp)   = make_float4(sp[0], sp[1], sp[2], sp[3]);
            *reinterpret_cast<float4*>(yp+4) = make_float4(sp[4], sp[5], sp[6], sp[7]);
        }
    }
}

// ---------------- TIM up-conv + bn1 + fused LIF1 ----------------------------------------
// grid (c=256, b=4, br=3), 256 threads = one (h,w) pixel. Weights in smem, f32x2 acc.
// After conv, all 40 j-channels are in registers; the LIF1 scan (j=4s+q) runs per q.
__global__ void upconv_lif_kernel(const float* __restrict__ A, float* __restrict__ S1) {
    extern __shared__ float sm[];
    float* As  = sm;          // [10][3][18][18] = 9720
    float* Wsm = sm + 9720;   // [270][40]       = 10800
    const int c = blockIdx.x, b = blockIdx.y, br = blockIdx.z;
    const float* Ab = A + (size_t)br * BR_STRIDE_A;
    float* Sb = S1 + (size_t)br * BR_STRIDE_U;
    const int tid = threadIdx.x;
    for (int i = tid; i < 10800; i += 256) Wsm[i] = g_WupT[i];
    for (int idx = tid; idx < 9720; idx += 256) {
        int t = idx / 972, q = idx % 972;
        int dc = q / 324, q2 = q % 324;
        int hh = q2 / 18, ww = q2 % 18;
        int cc = c - 1 + dc;
        float v = 0.f;
        if (cc >= 0 && cc < 256 && hh >= 1 && hh <= 16 && ww >= 1 && ww <= 16)
            v = Ab[((t*4 + b)*256 + cc)*256 + (hh-1)*16 + (ww-1)];
        As[idx] = v;
    }
    __syncthreads();
    const int h = tid >> 4, w = tid & 15;
    u64 acc[20];
    #pragma unroll
    for (int j = 0; j < 20; j++) acc[j] = 0ull;
    for (int t = 0; t < 10; t++) {
        const float* at = As + t*972 + h*18 + w;
        const u64* wt = reinterpret_cast<const u64*>(Wsm) + t*540;
        #pragma unroll
        for (int dc = 0; dc < 3; dc++)
            #pragma unroll
            for (int dh = 0; dh < 3; dh++)
                #pragma unroll
                for (int dw = 0; dw < 3; dw++) {
                    float a = at[dc*324 + dh*18 + dw];
                    u64 a2; PACK2(a2, a, a);
                    const u64* wp = wt + (dc*9 + dh*3 + dw)*20;
                    #pragma unroll
                    for (int j = 0; j < 20; j++) FMA2(acc[j], a2, wp[j]);
                }
    }
    float av[40];
    #pragma unroll
    for (int p = 0; p < 20; p++) {
        float lo, hi; UNPACK2(lo, hi, acc[p]);
        av[2*p] = lo; av[2*p+1] = hi;
    }
    // fused LIF1: scan s over j = 4s+q, membrane per q
    #pragma unroll
    for (int q = 0; q < 4; q++) {
        float memv = 0.f;
        #pragma unroll
        for (int s = 0; s < 10; s++) {
            int j = 4*s + q;
            float x = g_bn1s[j]*av[j] + g_bn1o[j];
            memv += 0.5f*(x - memv);
            float sp = memv > 1.0f ? 1.f : 0.f;
            Sb[((b*40 + j)*256 + c)*256 + tid] = sp;
            if (sp > 0.f) memv = 0.f;
        }
    }
}

// ---------------- TIM down-conv (grouped) + bn2 + fused LIF2 ----------------------------
// grid (c=256, b=4, br=3), 256 threads; internal t-loop, membrane in register.
__global__ void downconv_lif_kernel(const float* __restrict__ S1, const float* __restrict__ Wd_g,
                                    const float* __restrict__ bn2, float* __restrict__ Out) {
    const int c = blockIdx.x, b = blockIdx.y, br = blockIdx.z;
    const float* Sb = S1 + (size_t)br * BR_STRIDE_U;
    float* Ob = Out + (size_t)br * BR_STRIDE_A;
    __shared__ float Ss[3888];   // [r=4][dc=3][18][18]
    __shared__ float Wd[1080];
    __shared__ float s_sc[10], s_of[10];
    const int tid = threadIdx.x;
    for (int i = tid; i < 1080; i += 256) Wd[i] = Wd_g[i];
    if (tid < 10) {
        float gm = bn2[tid], bt = bn2[10+tid], mu = bn2[20+tid], vr = bn2[30+tid];
        float s = gm * rsqrtf(vr + EPSF);
        s_sc[tid] = s; s_of[tid] = bt - mu*s;
    }
    const int h = tid >> 4, w = tid & 15;
    float memv = 0.f;
    __syncthreads();
    for (int t = 0; t < 10; t++) {
        for (int idx = tid; idx < 3888; idx += 256) {
            int r = idx / 972, q = idx % 972;
            int dc = q / 324, q2 = q % 324;
            int hh = q2 / 18, ww = q2 % 18;
            int cc = c - 1 + dc;
            float v = 0.f;
            if (cc >= 0 && cc < 256 && hh >= 1 && hh <= 16 && ww >= 1 && ww <= 16)
                v = Sb[((b*40 + 4*t + r)*256 + cc)*256 + (hh-1)*16 + (ww-1)];
            Ss[idx] = v;
        }
        __syncthreads();
        float acc = 0.f;
        const float* wt = Wd + t*108;
        #pragma unroll
        for (int r = 0; r < 4; r++)
            #pragma unroll
            for (int dc = 0; dc < 3; dc++)
                #pragma unroll
                for (int dh = 0; dh < 3; dh++)
                    #pragma unroll
                    for (int dw = 0; dw < 3; dw++)
                        acc += wt[r*27 + dc*9 + dh*3 + dw] *
                               Ss[r*972 + dc*324 + (h+dh)*18 + (w+dw)];
        float x = s_sc[t]*acc + s_of[t];
        memv += 0.5f*(x - memv);
        float sp = memv > 1.0f ? 1.f : 0.f;
        Ob[(t*4 + b)*65536 + c*256 + tid] = sp;
        if (sp > 0.f) memv = 0.f;
        __syncthreads();
    }
}

// ---------------- attention via G = K^T V (exact for binary spikes) + fused attn-LIF ----
// grid (h=16, b=4), 256 threads. Per t: G[16][16] = K^T V; o = Q G * 0.25; LIF over t.
__global__ void attn_lif_kernel(const float* __restrict__ Qp, const float* __restrict__ Kp,
                                const float* __restrict__ Vp, float* __restrict__ SpO) {
    const int hh = blockIdx.x, b = blockIdx.y;
    __shared__ __align__(16) float Ks[256*17];
    __shared__ __align__(16) float Vs[256*17];
    __shared__ __align__(16) float Gs[16*18];
    const int tid = threadIdx.x;
    const int d1 = tid >> 4, d2 = tid & 15;
    float memv[16];
    #pragma unroll
    for (int d = 0; d < 16; d++) memv[d] = 0.f;

    for (int t = 0; t < 10; t++) {
        const int base = (t*4 + b)*65536 + hh*4096;
        for (int idx = tid; idx < 4096; idx += 256) {
            int dd = idx >> 8, m = idx & 255;
            Ks[m*17 + dd] = Kp[base + dd*256 + m];
            Vs[m*17 + dd] = Vp[base + dd*256 + m];
        }
        __syncthreads();
        // G[d1][d2] = sum_m K[m,d1] * V[m,d2]
        float g = 0.f;
        #pragma unroll 8
        for (int m = 0; m < 256; m++)
            g += Ks[m*17 + d1] * Vs[m*17 + d2];
        Gs[d1*18 + d2] = g;
        __syncthreads();
        // o[n,d] = sum_d1 Q[d1,n] * G[d1,d], then *0.25 and LIF
        const int n = tid;
        u64 o2[8];
        #pragma unroll
        for (int i = 0; i < 8; i++) o2[i] = 0ull;
        #pragma unroll
        for (int dd1 = 0; dd1 < 16; dd1++) {
            float q = Qp[base + dd1*256 + n];
            u64 q2; PACK2(q2, q, q);
            const u64* gp = reinterpret_cast<const u64*>(&Gs[dd1*18]);
            #pragma unroll
            for (int i = 0; i < 8; i++) FMA2(o2[i], q2, gp[i]);
        }
        #pragma unroll
        for (int i = 0; i < 8; i++) {
            float lo, hi; UNPACK2(lo, hi, o2[i]);
            int da = 2*i, db = 2*i+1;
            float xa = 0.25f*lo, xb = 0.25f*hi;
            float ma = memv[da] + 0.5f*(xa - memv[da]);
            float spa = ma > 0.5f ? 1.f : 0.f;
            memv[da] = (spa > 0.f) ? 0.f : ma;
            SpO[base + da*256 + n] = spa;
            float mb = memv[db] + 0.5f*(xb - memv[db]);
            float spb = mb > 0.5f ? 1.f : 0.f;
            memv[db] = (spb > 0.f) ? 0.f : mb;
            SpO[base + db*256 + n] = spb;
        }
        __syncthreads();
    }
}

// ---------------- standard LIF over leading T dim, layout (t,b,C,n); optional residual ----
__global__ void lif_std_kernel(const float* __restrict__ in, float* __restrict__ out,
                               const float* __restrict__ res, int Cch, float vth) {
    int idx = blockIdx.x*256 + threadIdx.x;
    int per_b = Cch*256;
    int b = idx / per_b, cn = idx - b*per_b;
    float mem = 0.f;
    #pragma unroll
    for (int t = 0; t < 10; t++) {
        int off = (t*4 + b)*per_b + cn;
        float x = in[off];
        mem += 0.5f*(x - mem);
        float sp = mem > vth ? 1.f : 0.f;
        out[off] = res ? res[off] + sp : sp;
        if (sp > 0.f) mem = 0.f;
    }
}

// ---------------- launch ----------------
extern "C" void kernel_launch(void* const* d_in, const int* in_sizes, int n_in,
                              void* d_out, int out_size) {
    const float* x        = (const float*)d_in[0];
    const float* q_w      = (const float*)d_in[1];
    const float* q_bn     = (const float*)d_in[2];
    const float* k_w      = (const float*)d_in[3];
    const float* k_bn     = (const float*)d_in[4];
    const float* v_w      = (const float*)d_in[5];
    const float* v_bn     = (const float*)d_in[6];
    const float* proj_w   = (const float*)d_in[7];
    const float* proj_bn  = (const float*)d_in[8];
    const float* tim_up_w = (const float*)d_in[9];
    const float* tim_bn1  = (const float*)d_in[10];
    const float* tim_dn_w = (const float*)d_in[11];
    const float* tim_bn2  = (const float*)d_in[12];
    const float* fc1_w    = (const float*)d_in[13];
    const float* fc1_b    = (const float*)d_in[14];
    const float* fc1_bn   = (const float*)d_in[15];
    const float* fc2_w    = (const float*)d_in[16];
    const float* fc2_b    = (const float*)d_in[17];
    const float* fc2_bn   = (const float*)d_in[18];
    float* out = (float*)d_out;

    float *bA,*bS1,*bQKV,*bSpO,*bP,*bH,*bS2,*bF2;
    cudaGetSymbolAddress((void**)&bA,   g_A);
    cudaGetSymbolAddress((void**)&bS1,  g_S1);
    cudaGetSymbolAddress((void**)&bQKV, g_QKV);
    cudaGetSymbolAddress((void**)&bSpO, g_SpO);
    cudaGetSymbolAddress((void**)&bP,   g_P);
    cudaGetSymbolAddress((void**)&bH,   g_H);
    cudaGetSymbolAddress((void**)&bS2,  g_S2);
    cudaGetSymbolAddress((void**)&bF2,  g_F2);

    cudaFuncSetAttribute(upconv_lif_kernel, cudaFuncAttributeMaxDynamicSharedMemorySize, 82080);

    prep_kernel<<<43, 256>>>(tim_up_w, tim_bn1);

    // --- q/k/v branches, fused TIM pipeline ---
    gemm_bn_kernel<256><<<dim3(2,4,120), 256>>>(x, q_w, k_w, v_w, q_bn, k_bn, v_bn,
                                                nullptr, bA, 256);
    upconv_lif_kernel<<<dim3(256,4,3), 256, 82080>>>(bA, bS1);
    downconv_lif_kernel<<<dim3(256,4,3), 256>>>(bS1, tim_dn_w, tim_bn2, bQKV);

    // --- attention (G-trick, exact) + attn-LIF fused ---
    attn_lif_kernel<<<dim3(16,4), 256>>>(bQKV, bQKV + BR_STRIDE_A, bQKV + 2*BR_STRIDE_A, bSpO);

    // --- proj + residual ---
    gemm_bn_kernel<256><<<dim3(2,4,40), 256>>>(bSpO, proj_w, proj_w, proj_w,
                                               proj_bn, proj_bn, proj_bn, nullptr, bP, 256);
    lif_std_kernel<<<1024, 256>>>(bP, bH, x, 256, 1.0f);   // h = x + ssa

    // --- mlp: fc1 fused with LIF; fc2 + final LIF with residual ---
    gemm_lif_kernel<256><<<dim3(2,16,4), 256>>>(bH, fc1_w, fc1_bn, fc1_b, bS2, 1024);
    gemm_bn_kernel<1024><<<dim3(2,4,40), 256>>>(bS2, fc2_w, fc2_w, fc2_w,
                                                fc2_bn, fc2_bn, fc2_bn, fc2_b, bF2, 256);
    lif_std_kernel<<<1024, 256>>>(bF2, out, bH, 256, 1.0f);
}

// round 8
// speedup vs baseline: 1.5498x; 1.1250x over previous
#include <cuda_runtime.h>

#define TT 10
#define BB 4
#define CCH 256
#define NPIX 256
#define HIDN 1024
#define TRJ 40
#define EPSF 1e-5f

typedef unsigned long long u64;

// f32x2 packed-math helpers (sm_103a)
#define FMA2(d,a,b)    asm("fma.rn.f32x2 %0, %1, %2, %0;" : "+l"(d) : "l"(a), "l"(b))
#define FMA2N(d,a,b,c) asm("fma.rn.f32x2 %0, %1, %2, %3;" : "=l"(d) : "l"(a), "l"(b), "l"(c))
#define PACK2(d,lo,hi) asm("mov.b64 %0, {%1, %2};" : "=l"(d) : "f"(lo), "f"(hi))
#define UNPACK2(lo,hi,s) asm("mov.b64 {%0, %1}, %2;" : "=f"(lo), "=f"(hi) : "l"(s))

#define BR_STRIDE_A  2621440     // 10*4*256*256
#define BR_STRIDE_U  10485760    // 4*40*256*256

// ---------------- scratch (device globals; no runtime allocation) ----------------
__device__ float g_A  [3*TT*BB*CCH*NPIX];   // branch gemm+bn out   (br,t,b,c,n)
__device__ float g_S1 [3*BB*TRJ*CCH*NPIX];  // lif1 spikes          (br,b,j,c,n)
__device__ float g_QKV[3*TT*BB*CCH*NPIX];   // q/k/v spikes         (br,t,b,c,n)
__device__ float g_O  [TT*BB*CCH*NPIX];     // attention out
__device__ float g_SpO[TT*BB*CCH*NPIX];     // attn_lif spikes
__device__ float g_P  [TT*BB*CCH*NPIX];     // proj gemm+bn
__device__ float g_H  [TT*BB*CCH*NPIX];     // residual h = x + ssa
__device__ float g_S2 [TT*BB*HIDN*NPIX];    // fc1 spikes
__device__ float g_F2 [TT*BB*CCH*NPIX];     // fc2 out
__device__ float g_WupT[270*40];            // transposed up-conv weights (tap-major)
__device__ float g_bn1s[40], g_bn1o[40];

// ---------------- prep: transpose up-conv weights, fold bn1 ----------------
__global__ void prep_kernel(const float* __restrict__ up_w, const float* __restrict__ bn1) {
    for (int idx = blockIdx.x*blockDim.x + threadIdx.x; idx < 10800;
         idx += gridDim.x*blockDim.x) {
        int j = idx / 270, r = idx % 270;
        g_WupT[r*40 + j] = up_w[idx];
    }
    int i = blockIdx.x*blockDim.x + threadIdx.x;
    if (i < 40) {
        float gm = bn1[i], bt = bn1[40+i], mu = bn1[80+i], vr = bn1[120+i];
        float s = gm * rsqrtf(vr + EPSF);
        g_bn1s[i] = s; g_bn1o[i] = bt - mu*s;
    }
}

// ---------------- batched GEMM + BN (+bias), f32x2 accumulation -----------------
// Y[br,g,o,n] = bn(W_br[o,:] @ X[g,:,n] + bias). 64x128 tile, BK=16, 256 thr.
template<int CIN>
__global__ void gemm_bn_kernel(const float* __restrict__ X,
        const float* __restrict__ W0, const float* __restrict__ W1, const float* __restrict__ W2,
        const float* __restrict__ B0, const float* __restrict__ B1, const float* __restrict__ B2,
        const float* __restrict__ bias, float* __restrict__ Y, int Cout) {
    const int zz = blockIdx.z;
    const int br = zz / 40, g = zz - br*40;
    const float* W   = (br == 0) ? W0 : ((br == 1) ? W1 : W2);
    const float* bnp = (br == 0) ? B0 : ((br == 1) ? B1 : B2);
    float* Yb = Y + (size_t)br * 40 * Cout * 256;
    const int mo = blockIdx.y*64, no = blockIdx.x*128;
    __shared__ __align__(16) float Ws[16][64];
    __shared__ __align__(16) float Xs[16][128];
    const int tid = threadIdx.x;
    const int tx = tid & 15, ty = tid >> 4;
    u64 acc[4][4];
    #pragma unroll
    for (int i = 0; i < 4; i++)
        #pragma unroll
        for (int j = 0; j < 4; j++) acc[i][j] = 0ull;
    const float* Xg = X + (size_t)g*CIN*256;
    for (int k0 = 0; k0 < CIN; k0 += 16) {
        {
            int m = tid >> 2, kq = (tid & 3)*4;
            float4 w4 = *reinterpret_cast<const float4*>(&W[(mo+m)*CIN + k0 + kq]);
            Ws[kq+0][m] = w4.x; Ws[kq+1][m] = w4.y; Ws[kq+2][m] = w4.z; Ws[kq+3][m] = w4.w;
        }
        {
            int kr = tid >> 4, nq = (tid & 15)*8;
            *reinterpret_cast<float4*>(&Xs[kr][nq]) =
                *reinterpret_cast<const float4*>(&Xg[(k0+kr)*256 + no + nq]);
            *reinterpret_cast<float4*>(&Xs[kr][nq+4]) =
                *reinterpret_cast<const float4*>(&Xg[(k0+kr)*256 + no + nq + 4]);
        }
        __syncthreads();
        #pragma unroll
        for (int kk = 0; kk < 16; kk++) {
            u64 a2[4];
            #pragma unroll
            for (int i = 0; i < 4; i++) { float a = Ws[kk][ty*4+i]; PACK2(a2[i], a, a); }
            ulonglong2 bb0 = *reinterpret_cast<const ulonglong2*>(&Xs[kk][tx*8]);
            ulonglong2 bb1 = *reinterpret_cast<const ulonglong2*>(&Xs[kk][tx*8+4]);
            u64 b2[4] = {bb0.x, bb0.y, bb1.x, bb1.y};
            #pragma unroll
            for (int i = 0; i < 4; i++)
                #pragma unroll
                for (int j = 0; j < 4; j++)
                    FMA2(acc[i][j], a2[i], b2[j]);
        }
        __syncthreads();
    }
    #pragma unroll
    for (int i = 0; i < 4; i++) {
        int o = mo + ty*4 + i;
        float gm = bnp[o], bt = bnp[Cout+o], mu = bnp[2*Cout+o], vr = bnp[3*Cout+o];
        float s = gm * rsqrtf(vr + EPSF);
        float off = bt - mu*s + (bias ? s*bias[o] : 0.f);
        u64 s2, o2; PACK2(s2, s, s); PACK2(o2, off, off);
        float r[8];
        #pragma unroll
        for (int j = 0; j < 4; j++) {
            u64 d; FMA2N(d, acc[i][j], s2, o2);
            UNPACK2(r[2*j], r[2*j+1], d);
        }
        float* yp = &Yb[((size_t)g*Cout + o)*256 + no + tx*8];
        *reinterpret_cast<float4*>(yp)   = make_float4(r[0], r[1], r[2], r[3]);
        *reinterpret_cast<float4*>(yp+4) = make_float4(r[4], r[5], r[6], r[7]);
    }
}

// ---------------- GEMM + BN + bias + fused LIF over t, 64x64 tiles (fc1) ----------------
// grid (4, Cout/64, b=4); internal t-loop with membrane in registers; writes spikes.
template<int CIN>
__global__ void gemm_lif_kernel(const float* __restrict__ X, const float* __restrict__ W,
                                const float* __restrict__ bnp, const float* __restrict__ bias,
                                float* __restrict__ Y, int Cout) {
    const int b = blockIdx.z;
    const int mo = blockIdx.y*64, no = blockIdx.x*64;
    __shared__ __align__(16) float Ws[16][64];
    __shared__ __align__(16) float Xs[16][64];
    const int tid = threadIdx.x;
    const int tx = tid & 15, ty = tid >> 4;
    float bns[4], bno[4];
    #pragma unroll
    for (int i = 0; i < 4; i++) {
        int o = mo + ty*4 + i;
        float gm = bnp[o], bt = bnp[Cout+o], mu = bnp[2*Cout+o], vr = bnp[3*Cout+o];
        float s = gm * rsqrtf(vr + EPSF);
        bns[i] = s; bno[i] = bt - mu*s + (bias ? s*bias[o] : 0.f);
    }
    float mem[4][4];
    #pragma unroll
    for (int i = 0; i < 4; i++)
        #pragma unroll
        for (int j = 0; j < 4; j++) mem[i][j] = 0.f;

    for (int t = 0; t < 10; t++) {
        const float* Xg = X + ((size_t)(t*4 + b))*CIN*256;
        u64 acc[4][2];
        #pragma unroll
        for (int i = 0; i < 4; i++) { acc[i][0] = 0ull; acc[i][1] = 0ull; }
        for (int k0 = 0; k0 < CIN; k0 += 16) {
            {
                int m = tid >> 2, kq = (tid & 3)*4;
                float4 w4 = *reinterpret_cast<const float4*>(&W[(mo+m)*CIN + k0 + kq]);
                Ws[kq+0][m] = w4.x; Ws[kq+1][m] = w4.y; Ws[kq+2][m] = w4.z; Ws[kq+3][m] = w4.w;
            }
            {
                int kr = tid >> 4, nq = (tid & 15)*4;
                *reinterpret_cast<float4*>(&Xs[kr][nq]) =
                    *reinterpret_cast<const float4*>(&Xg[(k0+kr)*256 + no + nq]);
            }
            __syncthreads();
            #pragma unroll
            for (int kk = 0; kk < 16; kk++) {
                u64 a2[4];
                #pragma unroll
                for (int i = 0; i < 4; i++) { float a = Ws[kk][ty*4+i]; PACK2(a2[i], a, a); }
                ulonglong2 bb = *reinterpret_cast<const ulonglong2*>(&Xs[kk][tx*4]);
                #pragma unroll
                for (int i = 0; i < 4; i++) {
                    FMA2(acc[i][0], a2[i], bb.x);
                    FMA2(acc[i][1], a2[i], bb.y);
                }
            }
            __syncthreads();
        }
        #pragma unroll
        for (int i = 0; i < 4; i++) {
            int o = mo + ty*4 + i;
            float r[4];
            #pragma unroll
            for (int j = 0; j < 2; j++) {
                float lo, hi; UNPACK2(lo, hi, acc[i][j]);
                r[2*j] = bns[i]*lo + bno[i]; r[2*j+1] = bns[i]*hi + bno[i];
            }
            float sp[4];
            #pragma unroll
            for (int j = 0; j < 4; j++) {
                float m2 = mem[i][j] + 0.5f*(r[j] - mem[i][j]);
                float s = m2 > 1.0f ? 1.f : 0.f;
                sp[j] = s;
                mem[i][j] = (s > 0.f) ? 0.f : m2;
            }
            float* yp = &Y[((size_t)(t*4 + b)*Cout + o)*256 + no + tx*4];
            *reinterpret_cast<float4*>(yp) = make_float4(sp[0], sp[1], sp[2], sp[3]);
        }
    }
}

// ---------------- TIM up-conv + bn1 + fused LIF1 ----------------------------------------
// grid (c=256, b=4, br=3), 256 threads = one (h,w) pixel. Weights in smem (LDS.128),
// f32x2 accumulation. Dynamic smem = 82080 B.
__global__ void upconv_lif_kernel(const float* __restrict__ A, float* __restrict__ S1) {
    extern __shared__ __align__(16) float sm[];
    float* As  = sm;          // [10][3][18][18] = 9720
    float* Wsm = sm + 9720;   // [270][40]       = 10800 (byte off 38880, 16B aligned)
    const int c = blockIdx.x, b = blockIdx.y, br = blockIdx.z;
    const float* Ab = A + (size_t)br * BR_STRIDE_A;
    float* Sb = S1 + (size_t)br * BR_STRIDE_U;
    const int tid = threadIdx.x;
    for (int i = tid; i < 10800; i += 256) Wsm[i] = g_WupT[i];
    for (int idx = tid; idx < 9720; idx += 256) {
        int t = idx / 972, q = idx % 972;
        int dc = q / 324, q2 = q % 324;
        int hh = q2 / 18, ww = q2 % 18;
        int cc = c - 1 + dc;
        float v = 0.f;
        if (cc >= 0 && cc < 256 && hh >= 1 && hh <= 16 && ww >= 1 && ww <= 16)
            v = Ab[((t*4 + b)*256 + cc)*256 + (hh-1)*16 + (ww-1)];
        As[idx] = v;
    }
    __syncthreads();
    const int h = tid >> 4, w = tid & 15;
    u64 acc[20];
    #pragma unroll
    for (int j = 0; j < 20; j++) acc[j] = 0ull;
    for (int t = 0; t < 10; t++) {
        const float* at = As + t*972 + h*18 + w;
        const u64* wt = reinterpret_cast<const u64*>(Wsm) + t*540;
        #pragma unroll
        for (int dc = 0; dc < 3; dc++)
            #pragma unroll
            for (int dh = 0; dh < 3; dh++)
                #pragma unroll
                for (int dw = 0; dw < 3; dw++) {
                    float a = at[dc*324 + dh*18 + dw];
                    u64 a2; PACK2(a2, a, a);
                    const ulonglong2* wp2 =
                        reinterpret_cast<const ulonglong2*>(wt + (dc*9 + dh*3 + dw)*20);
                    #pragma unroll
                    for (int j2 = 0; j2 < 10; j2++) {
                        ulonglong2 wv = wp2[j2];
                        FMA2(acc[2*j2  ], a2, wv.x);
                        FMA2(acc[2*j2+1], a2, wv.y);
                    }
                }
    }
    float av[40];
    #pragma unroll
    for (int p = 0; p < 20; p++) {
        float lo, hi; UNPACK2(lo, hi, acc[p]);
        av[2*p] = lo; av[2*p+1] = hi;
    }
    // fused LIF1: scan s over j = 4s+q, membrane per q
    #pragma unroll
    for (int q = 0; q < 4; q++) {
        float memv = 0.f;
        #pragma unroll
        for (int s = 0; s < 10; s++) {
            int j = 4*s + q;
            float x = g_bn1s[j]*av[j] + g_bn1o[j];
            memv += 0.5f*(x - memv);
            float sp = memv > 1.0f ? 1.f : 0.f;
            Sb[((b*40 + j)*256 + c)*256 + tid] = sp;
            if (sp > 0.f) memv = 0.f;
        }
    }
}

// ---------------- TIM down-conv (grouped) + bn2 + fused LIF2, t-paired f32x2 ------------
// grid (c=256, b=4, br=3), 256 threads. Fill offsets precomputed once; 5 t-pair steps.
__global__ void downconv_lif_kernel(const float* __restrict__ S1, const float* __restrict__ Wd_g,
                                    const float* __restrict__ bn2, float* __restrict__ Out) {
    const int c = blockIdx.x, b = blockIdx.y, br = blockIdx.z;
    const float* Sb = S1 + (size_t)br * BR_STRIDE_U;
    float* Ob = Out + (size_t)br * BR_STRIDE_A;
    __shared__ __align__(16) u64 Ss[3888];     // spike pairs {t0,t1} per halo slot
    __shared__ __align__(16) u64 Wd2[540];     // weight pairs {w_t0,w_t1}[108] per tp
    __shared__ float s_sc[10], s_of[10];
    const int tid = threadIdx.x;
    for (int i = tid; i < 540; i += 256) {
        int p = i / 108, k = i - p*108;
        u64 d; PACK2(d, Wd_g[(2*p)*108 + k], Wd_g[(2*p+1)*108 + k]);
        Wd2[i] = d;
    }
    if (tid < 10) {
        float gm = bn2[tid], bt = bn2[10+tid], mu = bn2[20+tid], vr = bn2[30+tid];
        float s = gm * rsqrtf(vr + EPSF);
        s_sc[tid] = s; s_of[tid] = bt - mu*s;
    }
    // precompute fill descriptors (once; no integer div in the hot loop)
    int off0[16];
    #pragma unroll
    for (int s = 0; s < 16; s++) {
        int idx = tid + s*256;
        if (idx < 3888) {
            int r = idx / 972, q = idx - r*972;
            int dc = q / 324, q2 = q - dc*324;
            int hh = q2 / 18, ww = q2 - hh*18;
            int cc = c - 1 + dc;
            bool valid = (cc >= 0 && cc < 256 && hh >= 1 && hh <= 16 && ww >= 1 && ww <= 16);
            off0[s] = valid ? (((b*40 + r)*256 + cc)*256 + (hh-1)*16 + (ww-1)) : -1;
        } else off0[s] = -2;
    }
    const int h = tid >> 4, w = tid & 15;
    const int sbase = h*18 + w;
    float memv = 0.f;
    for (int p = 0; p < 5; p++) {
        __syncthreads();
        const int tof = p*524288;   // 2p * 4 * 65536
        #pragma unroll
        for (int s = 0; s < 16; s++) {
            if (off0[s] != -2) {
                u64 d = 0ull;
                if (off0[s] >= 0) {
                    float v0 = Sb[off0[s] + tof];
                    float v1 = Sb[off0[s] + tof + 262144];
                    PACK2(d, v0, v1);
                }
                Ss[tid + s*256] = d;
            }
        }
        __syncthreads();
        u64 acc2 = 0ull;
        const u64* wt = Wd2 + p*108;
        #pragma unroll
        for (int r = 0; r < 4; r++)
            #pragma unroll
            for (int dc = 0; dc < 3; dc++)
                #pragma unroll
                for (int dh = 0; dh < 3; dh++)
                    #pragma unroll
                    for (int dw = 0; dw < 3; dw++)
                        FMA2(acc2, wt[r*27 + dc*9 + dh*3 + dw],
                             Ss[r*972 + dc*324 + sbase + dh*18 + dw]);
        float o0, o1; UNPACK2(o0, o1, acc2);
        int t0 = 2*p, t1 = 2*p + 1;
        float x0 = s_sc[t0]*o0 + s_of[t0];
        memv += 0.5f*(x0 - memv);
        float sp0 = memv > 1.0f ? 1.f : 0.f;
        Ob[(t0*4 + b)*65536 + c*256 + tid] = sp0;
        if (sp0 > 0.f) memv = 0.f;
        float x1 = s_sc[t1]*o1 + s_of[t1];
        memv += 0.5f*(x1 - memv);
        float sp1 = memv > 1.0f ? 1.f : 0.f;
        Ob[(t1*4 + b)*65536 + c*256 + tid] = sp1;
        if (sp1 > 0.f) memv = 0.f;
    }
}

// ---------------- attention via G = K^T V (exact for binary spikes), per (h,b,t) --------
__global__ void attn_kernel(const float* __restrict__ Qp, const float* __restrict__ Kp,
                            const float* __restrict__ Vp, float* __restrict__ Op) {
    const int hh = blockIdx.x, b = blockIdx.y, t = blockIdx.z;
    __shared__ __align__(16) float Ks[256*17];
    __shared__ __align__(16) float Vs[256*17];
    __shared__ __align__(16) float Gs[16*18];
    const int tid = threadIdx.x;
    const int base = (t*4 + b)*65536 + hh*4096;
    for (int idx = tid; idx < 4096; idx += 256) {
        int dd = idx >> 8, m = idx & 255;
        Ks[m*17 + dd] = Kp[base + dd*256 + m];
        Vs[m*17 + dd] = Vp[base + dd*256 + m];
    }
    __syncthreads();
    const int d1 = tid >> 4, d2 = tid & 15;
    float g = 0.f;
    #pragma unroll 8
    for (int m = 0; m < 256; m++)
        g += Ks[m*17 + d1] * Vs[m*17 + d2];
    Gs[d1*18 + d2] = g;
    __syncthreads();
    const int n = tid;
    u64 o2[8];
    #pragma unroll
    for (int i = 0; i < 8; i++) o2[i] = 0ull;
    #pragma unroll
    for (int dd1 = 0; dd1 < 16; dd1++) {
        float q = Qp[base + dd1*256 + n];
        u64 q2; PACK2(q2, q, q);
        const u64* gp = reinterpret_cast<const u64*>(&Gs[dd1*18]);
        #pragma unroll
        for (int i = 0; i < 8; i++) FMA2(o2[i], q2, gp[i]);
    }
    #pragma unroll
    for (int i = 0; i < 8; i++) {
        float lo, hi; UNPACK2(lo, hi, o2[i]);
        Op[base + (2*i  )*256 + n] = 0.25f*lo;
        Op[base + (2*i+1)*256 + n] = 0.25f*hi;
    }
}

// ---------------- standard LIF over leading T dim, layout (t,b,C,n); optional residual ----
__global__ void lif_std_kernel(const float* __restrict__ in, float* __restrict__ out,
                               const float* __restrict__ res, int Cch, float vth) {
    int idx = blockIdx.x*256 + threadIdx.x;
    int per_b = Cch*256;
    int b = idx / per_b, cn = idx - b*per_b;
    float mem = 0.f;
    #pragma unroll
    for (int t = 0; t < 10; t++) {
        int off = (t*4 + b)*per_b + cn;
        float x = in[off];
        mem += 0.5f*(x - mem);
        float sp = mem > vth ? 1.f : 0.f;
        out[off] = res ? res[off] + sp : sp;
        if (sp > 0.f) mem = 0.f;
    }
}

// ---------------- launch ----------------
extern "C" void kernel_launch(void* const* d_in, const int* in_sizes, int n_in,
                              void* d_out, int out_size) {
    const float* x        = (const float*)d_in[0];
    const float* q_w      = (const float*)d_in[1];
    const float* q_bn     = (const float*)d_in[2];
    const float* k_w      = (const float*)d_in[3];
    const float* k_bn     = (const float*)d_in[4];
    const float* v_w      = (const float*)d_in[5];
    const float* v_bn     = (const float*)d_in[6];
    const float* proj_w   = (const float*)d_in[7];
    const float* proj_bn  = (const float*)d_in[8];
    const float* tim_up_w = (const float*)d_in[9];
    const float* tim_bn1  = (const float*)d_in[10];
    const float* tim_dn_w = (const float*)d_in[11];
    const float* tim_bn2  = (const float*)d_in[12];
    const float* fc1_w    = (const float*)d_in[13];
    const float* fc1_b    = (const float*)d_in[14];
    const float* fc1_bn   = (const float*)d_in[15];
    const float* fc2_w    = (const float*)d_in[16];
    const float* fc2_b    = (const float*)d_in[17];
    const float* fc2_bn   = (const float*)d_in[18];
    float* out = (float*)d_out;

    float *bA,*bS1,*bQKV,*bO,*bSpO,*bP,*bH,*bS2,*bF2;
    cudaGetSymbolAddress((void**)&bA,   g_A);
    cudaGetSymbolAddress((void**)&bS1,  g_S1);
    cudaGetSymbolAddress((void**)&bQKV, g_QKV);
    cudaGetSymbolAddress((void**)&bO,   g_O);
    cudaGetSymbolAddress((void**)&bSpO, g_SpO);
    cudaGetSymbolAddress((void**)&bP,   g_P);
    cudaGetSymbolAddress((void**)&bH,   g_H);
    cudaGetSymbolAddress((void**)&bS2,  g_S2);
    cudaGetSymbolAddress((void**)&bF2,  g_F2);

    cudaFuncSetAttribute(upconv_lif_kernel, cudaFuncAttributeMaxDynamicSharedMemorySize, 82080);

    prep_kernel<<<43, 256>>>(tim_up_w, tim_bn1);

    // --- q/k/v branches, fused TIM pipeline ---
    gemm_bn_kernel<256><<<dim3(2,4,120), 256>>>(x, q_w, k_w, v_w, q_bn, k_bn, v_bn,
                                                nullptr, bA, 256);
    upconv_lif_kernel<<<dim3(256,4,3), 256, 82080>>>(bA, bS1);
    downconv_lif_kernel<<<dim3(256,4,3), 256>>>(bS1, tim_dn_w, tim_bn2, bQKV);

    // --- attention (G-trick, exact), then attn-LIF ---
    attn_kernel<<<dim3(16,4,10), 256>>>(bQKV, bQKV + BR_STRIDE_A, bQKV + 2*BR_STRIDE_A, bO);
    lif_std_kernel<<<1024, 256>>>(bO, bSpO, nullptr, 256, 0.5f);

    // --- proj + residual ---
    gemm_bn_kernel<256><<<dim3(2,4,40), 256>>>(bSpO, proj_w, proj_w, proj_w,
                                               proj_bn, proj_bn, proj_bn, nullptr, bP, 256);
    lif_std_kernel<<<1024, 256>>>(bP, bH, x, 256, 1.0f);   // h = x + ssa

    // --- mlp: fc1 fused with LIF (64x64 tiles); fc2 + final LIF with residual ---
    gemm_lif_kernel<256><<<dim3(4,16,4), 256>>>(bH, fc1_w, fc1_bn, fc1_b, bS2, 1024);
    gemm_bn_kernel<1024><<<dim3(2,4,40), 256>>>(bS2, fc2_w, fc2_w, fc2_w,
                                                fc2_bn, fc2_bn, fc2_bn, fc2_b, bF2, 256);
    lif_std_kernel<<<1024, 256>>>(bF2, out, bH, 256, 1.0f);
}

// round 9
// speedup vs baseline: 1.8990x; 1.2253x over previous
#include <cuda_runtime.h>

#define TT 10
#define BB 4
#define CCH 256
#define NPIX 256
#define HIDN 1024
#define TRJ 40
#define EPSF 1e-5f

typedef unsigned long long u64;

// f32x2 packed-math helpers (sm_103a)
#define FMA2(d,a,b)    asm("fma.rn.f32x2 %0, %1, %2, %0;" : "+l"(d) : "l"(a), "l"(b))
#define FMA2N(d,a,b,c) asm("fma.rn.f32x2 %0, %1, %2, %3;" : "=l"(d) : "l"(a), "l"(b), "l"(c))
#define PACK2(d,lo,hi) asm("mov.b64 %0, {%1, %2};" : "=l"(d) : "f"(lo), "f"(hi))
#define UNPACK2(lo,hi,s) asm("mov.b64 {%0, %1}, %2;" : "=f"(lo), "=f"(hi) : "l"(s))

#define BR_STRIDE_A  2621440     // 10*4*256*256

// ---------------- scratch (device globals; no runtime allocation) ----------------
__device__ float g_A  [3*TT*BB*CCH*NPIX];   // branch gemm+bn out   (br,t,b,c,n)
__device__ u64   g_M  [3*BB*CCH*NPIX];      // lif1 spike masks     (br,b,c,n) 40 bits each
__device__ float g_QKV[3*TT*BB*CCH*NPIX];   // q/k/v spikes         (br,t,b,c,n)
__device__ float g_O  [TT*BB*CCH*NPIX];     // attention out
__device__ float g_SpO[TT*BB*CCH*NPIX];     // attn_lif spikes
__device__ float g_P  [TT*BB*CCH*NPIX];     // proj gemm+bn
__device__ float g_H  [TT*BB*CCH*NPIX];     // residual h = x + ssa
__device__ float g_S2 [TT*BB*HIDN*NPIX];    // fc1 spikes
__device__ float g_F2 [TT*BB*CCH*NPIX];     // fc2 out
__device__ float g_WupT[270*40];            // transposed up-conv weights (tap-major)
__device__ float g_bn1s[40], g_bn1o[40];

// ---------------- prep: transpose up-conv weights, fold bn1 ----------------
__global__ void prep_kernel(const float* __restrict__ up_w, const float* __restrict__ bn1) {
    for (int idx = blockIdx.x*blockDim.x + threadIdx.x; idx < 10800;
         idx += gridDim.x*blockDim.x) {
        int j = idx / 270, r = idx % 270;
        g_WupT[r*40 + j] = up_w[idx];
    }
    int i = blockIdx.x*blockDim.x + threadIdx.x;
    if (i < 40) {
        float gm = bn1[i], bt = bn1[40+i], mu = bn1[80+i], vr = bn1[120+i];
        float s = gm * rsqrtf(vr + EPSF);
        g_bn1s[i] = s; g_bn1o[i] = bt - mu*s;
    }
}

// ---------------- batched GEMM + BN (+bias), f32x2 accumulation -----------------
// Y[br,g,o,n] = bn(W_br[o,:] @ X[g,:,n] + bias). 64x128 tile, BK=16, 256 thr.
template<int CIN>
__global__ void gemm_bn_kernel(const float* __restrict__ X,
        const float* __restrict__ W0, const float* __restrict__ W1, const float* __restrict__ W2,
        const float* __restrict__ B0, const float* __restrict__ B1, const float* __restrict__ B2,
        const float* __restrict__ bias, float* __restrict__ Y, int Cout) {
    const int zz = blockIdx.z;
    const int br = zz / 40, g = zz - br*40;
    const float* W   = (br == 0) ? W0 : ((br == 1) ? W1 : W2);
    const float* bnp = (br == 0) ? B0 : ((br == 1) ? B1 : B2);
    float* Yb = Y + (size_t)br * 40 * Cout * 256;
    const int mo = blockIdx.y*64, no = blockIdx.x*128;
    __shared__ __align__(16) float Ws[16][64];
    __shared__ __align__(16) float Xs[16][128];
    const int tid = threadIdx.x;
    const int tx = tid & 15, ty = tid >> 4;
    u64 acc[4][4];
    #pragma unroll
    for (int i = 0; i < 4; i++)
        #pragma unroll
        for (int j = 0; j < 4; j++) acc[i][j] = 0ull;
    const float* Xg = X + (size_t)g*CIN*256;
    for (int k0 = 0; k0 < CIN; k0 += 16) {
        {
            int m = tid >> 2, kq = (tid & 3)*4;
            float4 w4 = *reinterpret_cast<const float4*>(&W[(mo+m)*CIN + k0 + kq]);
            Ws[kq+0][m] = w4.x; Ws[kq+1][m] = w4.y; Ws[kq+2][m] = w4.z; Ws[kq+3][m] = w4.w;
        }
        {
            int kr = tid >> 4, nq = (tid & 15)*8;
            *reinterpret_cast<float4*>(&Xs[kr][nq]) =
                *reinterpret_cast<const float4*>(&Xg[(k0+kr)*256 + no + nq]);
            *reinterpret_cast<float4*>(&Xs[kr][nq+4]) =
                *reinterpret_cast<const float4*>(&Xg[(k0+kr)*256 + no + nq + 4]);
        }
        __syncthreads();
        #pragma unroll
        for (int kk = 0; kk < 16; kk++) {
            u64 a2[4];
            #pragma unroll
            for (int i = 0; i < 4; i++) { float a = Ws[kk][ty*4+i]; PACK2(a2[i], a, a); }
            ulonglong2 bb0 = *reinterpret_cast<const ulonglong2*>(&Xs[kk][tx*8]);
            ulonglong2 bb1 = *reinterpret_cast<const ulonglong2*>(&Xs[kk][tx*8+4]);
            u64 b2[4] = {bb0.x, bb0.y, bb1.x, bb1.y};
            #pragma unroll
            for (int i = 0; i < 4; i++)
                #pragma unroll
                for (int j = 0; j < 4; j++)
                    FMA2(acc[i][j], a2[i], b2[j]);
        }
        __syncthreads();
    }
    #pragma unroll
    for (int i = 0; i < 4; i++) {
        int o = mo + ty*4 + i;
        float gm = bnp[o], bt = bnp[Cout+o], mu = bnp[2*Cout+o], vr = bnp[3*Cout+o];
        float s = gm * rsqrtf(vr + EPSF);
        float off = bt - mu*s + (bias ? s*bias[o] : 0.f);
        u64 s2, o2; PACK2(s2, s, s); PACK2(o2, off, off);
        float r[8];
        #pragma unroll
        for (int j = 0; j < 4; j++) {
            u64 d; FMA2N(d, acc[i][j], s2, o2);
            UNPACK2(r[2*j], r[2*j+1], d);
        }
        float* yp = &Yb[((size_t)g*Cout + o)*256 + no + tx*8];
        *reinterpret_cast<float4*>(yp)   = make_float4(r[0], r[1], r[2], r[3]);
        *reinterpret_cast<float4*>(yp+4) = make_float4(r[4], r[5], r[6], r[7]);
    }
}

// ---------------- GEMM + BN + bias + fused LIF over t, 64x64 tiles (fc1) ----------------
template<int CIN>
__global__ void gemm_lif_kernel(const float* __restrict__ X, const float* __restrict__ W,
                                const float* __restrict__ bnp, const float* __restrict__ bias,
                                float* __restrict__ Y, int Cout) {
    const int b = blockIdx.z;
    const int mo = blockIdx.y*64, no = blockIdx.x*64;
    __shared__ __align__(16) float Ws[16][64];
    __shared__ __align__(16) float Xs[16][64];
    const int tid = threadIdx.x;
    const int tx = tid & 15, ty = tid >> 4;
    float bns[4], bno[4];
    #pragma unroll
    for (int i = 0; i < 4; i++) {
        int o = mo + ty*4 + i;
        float gm = bnp[o], bt = bnp[Cout+o], mu = bnp[2*Cout+o], vr = bnp[3*Cout+o];
        float s = gm * rsqrtf(vr + EPSF);
        bns[i] = s; bno[i] = bt - mu*s + (bias ? s*bias[o] : 0.f);
    }
    float mem[4][4];
    #pragma unroll
    for (int i = 0; i < 4; i++)
        #pragma unroll
        for (int j = 0; j < 4; j++) mem[i][j] = 0.f;

    for (int t = 0; t < 10; t++) {
        const float* Xg = X + ((size_t)(t*4 + b))*CIN*256;
        u64 acc[4][2];
        #pragma unroll
        for (int i = 0; i < 4; i++) { acc[i][0] = 0ull; acc[i][1] = 0ull; }
        for (int k0 = 0; k0 < CIN; k0 += 16) {
            {
                int m = tid >> 2, kq = (tid & 3)*4;
                float4 w4 = *reinterpret_cast<const float4*>(&W[(mo+m)*CIN + k0 + kq]);
                Ws[kq+0][m] = w4.x; Ws[kq+1][m] = w4.y; Ws[kq+2][m] = w4.z; Ws[kq+3][m] = w4.w;
            }
            {
                int kr = tid >> 4, nq = (tid & 15)*4;
                *reinterpret_cast<float4*>(&Xs[kr][nq]) =
                    *reinterpret_cast<const float4*>(&Xg[(k0+kr)*256 + no + nq]);
            }
            __syncthreads();
            #pragma unroll
            for (int kk = 0; kk < 16; kk++) {
                u64 a2[4];
                #pragma unroll
                for (int i = 0; i < 4; i++) { float a = Ws[kk][ty*4+i]; PACK2(a2[i], a, a); }
                ulonglong2 bb = *reinterpret_cast<const ulonglong2*>(&Xs[kk][tx*4]);
                #pragma unroll
                for (int i = 0; i < 4; i++) {
                    FMA2(acc[i][0], a2[i], bb.x);
                    FMA2(acc[i][1], a2[i], bb.y);
                }
            }
            __syncthreads();
        }
        #pragma unroll
        for (int i = 0; i < 4; i++) {
            int o = mo + ty*4 + i;
            float r[4];
            #pragma unroll
            for (int j = 0; j < 2; j++) {
                float lo, hi; UNPACK2(lo, hi, acc[i][j]);
                r[2*j] = bns[i]*lo + bno[i]; r[2*j+1] = bns[i]*hi + bno[i];
            }
            float sp[4];
            #pragma unroll
            for (int j = 0; j < 4; j++) {
                float m2 = mem[i][j] + 0.5f*(r[j] - mem[i][j]);
                float s = m2 > 1.0f ? 1.f : 0.f;
                sp[j] = s;
                mem[i][j] = (s > 0.f) ? 0.f : m2;
            }
            float* yp = &Y[((size_t)(t*4 + b)*Cout + o)*256 + no + tx*4];
            *reinterpret_cast<float4*>(yp) = make_float4(sp[0], sp[1], sp[2], sp[3]);
        }
    }
}

// ---------------- TIM up-conv + bn1 + fused LIF1 -> 40-bit spike masks ------------------
// grid (c=256, b=4, br=3), 256 threads = one (h,w) pixel. Weights in smem (LDS.128),
// f32x2 accumulation. Emits ONE u64 mask per pixel (bit j = spike of channel j).
__global__ void upconv_lif_kernel(const float* __restrict__ A, u64* __restrict__ M) {
    extern __shared__ __align__(16) float sm[];
    float* As  = sm;          // [10][3][18][18] = 9720
    float* Wsm = sm + 9720;   // [270][40]       = 10800
    const int c = blockIdx.x, b = blockIdx.y, br = blockIdx.z;
    const float* Ab = A + (size_t)br * BR_STRIDE_A;
    const int tid = threadIdx.x;
    for (int i = tid; i < 10800; i += 256) Wsm[i] = g_WupT[i];
    for (int idx = tid; idx < 9720; idx += 256) {
        int t = idx / 972, q = idx % 972;
        int dc = q / 324, q2 = q % 324;
        int hh = q2 / 18, ww = q2 % 18;
        int cc = c - 1 + dc;
        float v = 0.f;
        if (cc >= 0 && cc < 256 && hh >= 1 && hh <= 16 && ww >= 1 && ww <= 16)
            v = Ab[((t*4 + b)*256 + cc)*256 + (hh-1)*16 + (ww-1)];
        As[idx] = v;
    }
    __syncthreads();
    const int h = tid >> 4, w = tid & 15;
    u64 acc[20];
    #pragma unroll
    for (int j = 0; j < 20; j++) acc[j] = 0ull;
    for (int t = 0; t < 10; t++) {
        const float* at = As + t*972 + h*18 + w;
        const u64* wt = reinterpret_cast<const u64*>(Wsm) + t*540;
        #pragma unroll
        for (int dc = 0; dc < 3; dc++)
            #pragma unroll
            for (int dh = 0; dh < 3; dh++)
                #pragma unroll
                for (int dw = 0; dw < 3; dw++) {
                    float a = at[dc*324 + dh*18 + dw];
                    u64 a2; PACK2(a2, a, a);
                    const ulonglong2* wp2 =
                        reinterpret_cast<const ulonglong2*>(wt + (dc*9 + dh*3 + dw)*20);
                    #pragma unroll
                    for (int j2 = 0; j2 < 10; j2++) {
                        ulonglong2 wv = wp2[j2];
                        FMA2(acc[2*j2  ], a2, wv.x);
                        FMA2(acc[2*j2+1], a2, wv.y);
                    }
                }
    }
    float av[40];
    #pragma unroll
    for (int p = 0; p < 20; p++) {
        float lo, hi; UNPACK2(lo, hi, acc[p]);
        av[2*p] = lo; av[2*p+1] = hi;
    }
    // fused LIF1: scan s over j = 4s+q, membrane per q; pack spikes into 40-bit mask
    u64 mask = 0ull;
    #pragma unroll
    for (int q = 0; q < 4; q++) {
        float memv = 0.f;
        #pragma unroll
        for (int s = 0; s < 10; s++) {
            int j = 4*s + q;
            float x = g_bn1s[j]*av[j] + g_bn1o[j];
            memv += 0.5f*(x - memv);
            if (memv > 1.0f) { mask |= (1ull << j); memv = 0.f; }
        }
    }
    M[((size_t)(br*4 + b)*256 + c)*256 + tid] = mask;
}

// ---------------- TIM down-conv from spike masks + bn2 + fused LIF2 ---------------------
// grid (c=256, b=4, br=3), 256 threads. Single coalesced fill of 972 masks, one sync.
// Per-tap group sums via 16-entry nibble LUT (27 taps x 10 t), exact partial sums.
__global__ void downconv_lif_kernel(const u64* __restrict__ Mg, const float* __restrict__ Wd_g,
                                    const float* __restrict__ bn2, float* __restrict__ Out) {
    const int c = blockIdx.x, b = blockIdx.y, br = blockIdx.z;
    const u64* Mb = Mg + (size_t)(br*4 + b)*65536;
    float* Ob = Out + (size_t)br * BR_STRIDE_A;
    __shared__ __align__(16) u64 Ms[972];       // [dc=3][18][18] masks
    __shared__ float LUT[4320];                 // [tap=27][t=10][nib=16]
    __shared__ float s_sc[10], s_of[10];
    const int tid = threadIdx.x;
    // LUT: partial sums of the 4 r-weights selected by nibble
    for (int i = tid; i < 4320; i += 256) {
        int tap = i / 160, rem = i - tap*160;
        int t = rem >> 4, nib = rem & 15;
        float v = 0.f;
        if (nib & 1) v += Wd_g[t*108 +  0 + tap];
        if (nib & 2) v += Wd_g[t*108 + 27 + tap];
        if (nib & 4) v += Wd_g[t*108 + 54 + tap];
        if (nib & 8) v += Wd_g[t*108 + 81 + tap];
        LUT[i] = v;
    }
    if (tid < 10) {
        float gm = bn2[tid], bt = bn2[10+tid], mu = bn2[20+tid], vr = bn2[30+tid];
        float s = gm * rsqrtf(vr + EPSF);
        s_sc[tid] = s; s_of[tid] = bt - mu*s;
    }
    // fill halo masks (zero padded)
    for (int i = tid; i < 972; i += 256) {
        int dc = i / 324, rem = i - dc*324;
        int hh = rem / 18, ww = rem - hh*18;
        int cc = c - 1 + dc;
        u64 m = 0ull;
        if (cc >= 0 && cc < 256 && hh >= 1 && hh <= 16 && ww >= 1 && ww <= 16)
            m = Mb[cc*256 + (hh-1)*16 + (ww-1)];
        Ms[i] = m;
    }
    __syncthreads();
    const int h = tid >> 4, w = tid & 15;
    float acc[10];
    #pragma unroll
    for (int t = 0; t < 10; t++) acc[t] = 0.f;
    #pragma unroll
    for (int dc = 0; dc < 3; dc++)
        #pragma unroll
        for (int dh = 0; dh < 3; dh++)
            #pragma unroll
            for (int dw = 0; dw < 3; dw++) {
                u64 m = Ms[dc*324 + (h+dh)*18 + (w+dw)];
                unsigned mlo = (unsigned)m, mhi = (unsigned)(m >> 32);
                const float* lt = LUT + (dc*9 + dh*3 + dw)*160;
                #pragma unroll
                for (int t = 0; t < 8; t++)
                    acc[t] += lt[t*16 + ((mlo >> (4*t)) & 15u)];
                acc[8] += lt[128 + (mhi & 15u)];
                acc[9] += lt[144 + ((mhi >> 4) & 15u)];
            }
    // fused LIF2 over t
    float memv = 0.f;
    #pragma unroll
    for (int t = 0; t < 10; t++) {
        float x = s_sc[t]*acc[t] + s_of[t];
        memv += 0.5f*(x - memv);
        float sp = memv > 1.0f ? 1.f : 0.f;
        Ob[(t*4 + b)*65536 + c*256 + tid] = sp;
        if (sp > 0.f) memv = 0.f;
    }
}

// ---------------- attention via G = K^T V (exact for binary spikes), per (h,b,t) --------
__global__ void attn_kernel(const float* __restrict__ Qp, const float* __restrict__ Kp,
                            const float* __restrict__ Vp, float* __restrict__ Op) {
    const int hh = blockIdx.x, b = blockIdx.y, t = blockIdx.z;
    __shared__ __align__(16) float Ks[256*17];
    __shared__ __align__(16) float Vs[256*17];
    __shared__ __align__(16) float Gs[16*18];
    const int tid = threadIdx.x;
    const int base = (t*4 + b)*65536 + hh*4096;
    for (int idx = tid; idx < 4096; idx += 256) {
        int dd = idx >> 8, m = idx & 255;
        Ks[m*17 + dd] = Kp[base + dd*256 + m];
        Vs[m*17 + dd] = Vp[base + dd*256 + m];
    }
    __syncthreads();
    const int d1 = tid >> 4, d2 = tid & 15;
    float g = 0.f;
    #pragma unroll 8
    for (int m = 0; m < 256; m++)
        g += Ks[m*17 + d1] * Vs[m*17 + d2];
    Gs[d1*18 + d2] = g;
    __syncthreads();
    const int n = tid;
    u64 o2[8];
    #pragma unroll
    for (int i = 0; i < 8; i++) o2[i] = 0ull;
    #pragma unroll
    for (int dd1 = 0; dd1 < 16; dd1++) {
        float q = Qp[base + dd1*256 + n];
        u64 q2; PACK2(q2, q, q);
        const u64* gp = reinterpret_cast<const u64*>(&Gs[dd1*18]);
        #pragma unroll
        for (int i = 0; i < 8; i++) FMA2(o2[i], q2, gp[i]);
    }
    #pragma unroll
    for (int i = 0; i < 8; i++) {
        float lo, hi; UNPACK2(lo, hi, o2[i]);
        Op[base + (2*i  )*256 + n] = 0.25f*lo;
        Op[base + (2*i+1)*256 + n] = 0.25f*hi;
    }
}

// ---------------- standard LIF over leading T dim, layout (t,b,C,n); optional residual ----
__global__ void lif_std_kernel(const float* __restrict__ in, float* __restrict__ out,
                               const float* __restrict__ res, int Cch, float vth) {
    int idx = blockIdx.x*256 + threadIdx.x;
    int per_b = Cch*256;
    int b = idx / per_b, cn = idx - b*per_b;
    float mem = 0.f;
    #pragma unroll
    for (int t = 0; t < 10; t++) {
        int off = (t*4 + b)*per_b + cn;
        float x = in[off];
        mem += 0.5f*(x - mem);
        float sp = mem > vth ? 1.f : 0.f;
        out[off] = res ? res[off] + sp : sp;
        if (sp > 0.f) mem = 0.f;
    }
}

// ---------------- launch ----------------
extern "C" void kernel_launch(void* const* d_in, const int* in_sizes, int n_in,
                              void* d_out, int out_size) {
    const float* x        = (const float*)d_in[0];
    const float* q_w      = (const float*)d_in[1];
    const float* q_bn     = (const float*)d_in[2];
    const float* k_w      = (const float*)d_in[3];
    const float* k_bn     = (const float*)d_in[4];
    const float* v_w      = (const float*)d_in[5];
    const float* v_bn     = (const float*)d_in[6];
    const float* proj_w   = (const float*)d_in[7];
    const float* proj_bn  = (const float*)d_in[8];
    const float* tim_up_w = (const float*)d_in[9];
    const float* tim_bn1  = (const float*)d_in[10];
    const float* tim_dn_w = (const float*)d_in[11];
    const float* tim_bn2  = (const float*)d_in[12];
    const float* fc1_w    = (const float*)d_in[13];
    const float* fc1_b    = (const float*)d_in[14];
    const float* fc1_bn   = (const float*)d_in[15];
    const float* fc2_w    = (const float*)d_in[16];
    const float* fc2_b    = (const float*)d_in[17];
    const float* fc2_bn   = (const float*)d_in[18];
    float* out = (float*)d_out;

    float *bA,*bQKV,*bO,*bSpO,*bP,*bH,*bS2,*bF2;
    u64 *bM;
    cudaGetSymbolAddress((void**)&bA,   g_A);
    cudaGetSymbolAddress((void**)&bM,   g_M);
    cudaGetSymbolAddress((void**)&bQKV, g_QKV);
    cudaGetSymbolAddress((void**)&bO,   g_O);
    cudaGetSymbolAddress((void**)&bSpO, g_SpO);
    cudaGetSymbolAddress((void**)&bP,   g_P);
    cudaGetSymbolAddress((void**)&bH,   g_H);
    cudaGetSymbolAddress((void**)&bS2,  g_S2);
    cudaGetSymbolAddress((void**)&bF2,  g_F2);

    cudaFuncSetAttribute(upconv_lif_kernel, cudaFuncAttributeMaxDynamicSharedMemorySize, 82080);

    prep_kernel<<<43, 256>>>(tim_up_w, tim_bn1);

    // --- q/k/v branches, fused TIM pipeline (spike masks between convs) ---
    gemm_bn_kernel<256><<<dim3(2,4,120), 256>>>(x, q_w, k_w, v_w, q_bn, k_bn, v_bn,
                                                nullptr, bA, 256);
    upconv_lif_kernel<<<dim3(256,4,3), 256, 82080>>>(bA, bM);
    downconv_lif_kernel<<<dim3(256,4,3), 256>>>(bM, tim_dn_w, tim_bn2, bQKV);

    // --- attention (G-trick, exact), then attn-LIF ---
    attn_kernel<<<dim3(16,4,10), 256>>>(bQKV, bQKV + BR_STRIDE_A, bQKV + 2*BR_STRIDE_A, bO);
    lif_std_kernel<<<1024, 256>>>(bO, bSpO, nullptr, 256, 0.5f);

    // --- proj + residual ---
    gemm_bn_kernel<256><<<dim3(2,4,40), 256>>>(bSpO, proj_w, proj_w, proj_w,
                                               proj_bn, proj_bn, proj_bn, nullptr, bP, 256);
    lif_std_kernel<<<1024, 256>>>(bP, bH, x, 256, 1.0f);   // h = x + ssa

    // --- mlp: fc1 fused with LIF (64x64 tiles); fc2 + final LIF with residual ---
    gemm_lif_kernel<256><<<dim3(4,16,4), 256>>>(bH, fc1_w, fc1_bn, fc1_b, bS2, 1024);
    gemm_bn_kernel<1024><<<dim3(2,4,40), 256>>>(bS2, fc2_w, fc2_w, fc2_w,
                                                fc2_bn, fc2_bn, fc2_bn, fc2_b, bF2, 256);
    lif_std_kernel<<<1024, 256>>>(bF2, out, bH, 256, 1.0f);
}

// round 10
// speedup vs baseline: 1.8996x; 1.0003x over previous
#include <cuda_runtime.h>

#define TT 10
#define BB 4
#define CCH 256
#define NPIX 256
#define HIDN 1024
#define TRJ 40
#define EPSF 1e-5f

typedef unsigned long long u64;

// f32x2 packed-math helpers (sm_103a)
#define FMA2(d,a,b)    asm("fma.rn.f32x2 %0, %1, %2, %0;" : "+l"(d) : "l"(a), "l"(b))
#define FMA2N(d,a,b,c) asm("fma.rn.f32x2 %0, %1, %2, %3;" : "=l"(d) : "l"(a), "l"(b), "l"(c))
#define PACK2(d,lo,hi) asm("mov.b64 %0, {%1, %2};" : "=l"(d) : "f"(lo), "f"(hi))
#define UNPACK2(lo,hi,s) asm("mov.b64 {%0, %1}, %2;" : "=f"(lo), "=f"(hi) : "l"(s))

#define BR_STRIDE_A  2621440     // 10*4*256*256

// ---------------- scratch (device globals; no runtime allocation) ----------------
__device__ float g_A  [3*TT*BB*CCH*NPIX];   // branch gemm+bn out   (br,t,b,c,n)
__device__ u64   g_M  [3*BB*CCH*NPIX];      // lif1 spike masks     (br,b,c,n) 40 bits each
__device__ float g_QKV[3*TT*BB*CCH*NPIX];   // q/k/v spikes         (br,t,b,c,n)
__device__ float g_O  [TT*BB*CCH*NPIX];     // attention out
__device__ float g_SpO[TT*BB*CCH*NPIX];     // attn_lif spikes
__device__ float g_P  [TT*BB*CCH*NPIX];     // proj gemm+bn
__device__ float g_H  [TT*BB*CCH*NPIX];     // residual h = x + ssa
__device__ float g_S2 [TT*BB*HIDN*NPIX];    // fc1 spikes
__device__ float g_F2 [TT*BB*CCH*NPIX];     // fc2 out
__device__ float g_WupT[270*40];            // transposed up-conv weights (tap-major)
__device__ float g_bn1s[40], g_bn1o[40];

// ---------------- prep: transpose up-conv weights, fold bn1 ----------------
__global__ void prep_kernel(const float* __restrict__ up_w, const float* __restrict__ bn1) {
    for (int idx = blockIdx.x*blockDim.x + threadIdx.x; idx < 10800;
         idx += gridDim.x*blockDim.x) {
        int j = idx / 270, r = idx % 270;
        g_WupT[r*40 + j] = up_w[idx];
    }
    int i = blockIdx.x*blockDim.x + threadIdx.x;
    if (i < 40) {
        float gm = bn1[i], bt = bn1[40+i], mu = bn1[80+i], vr = bn1[120+i];
        float s = gm * rsqrtf(vr + EPSF);
        g_bn1s[i] = s; g_bn1o[i] = bt - mu*s;
    }
}

// ---------------- batched GEMM + BN (+bias), f32x2 accumulation -----------------
// Y[br,g,o,n] = bn(W_br[o,:] @ X[g,:,n] + bias). 64x128 tile, BK=16, 256 thr.
template<int CIN>
__global__ void gemm_bn_kernel(const float* __restrict__ X,
        const float* __restrict__ W0, const float* __restrict__ W1, const float* __restrict__ W2,
        const float* __restrict__ B0, const float* __restrict__ B1, const float* __restrict__ B2,
        const float* __restrict__ bias, float* __restrict__ Y, int Cout) {
    const int zz = blockIdx.z;
    const int br = zz / 40, g = zz - br*40;
    const float* W   = (br == 0) ? W0 : ((br == 1) ? W1 : W2);
    const float* bnp = (br == 0) ? B0 : ((br == 1) ? B1 : B2);
    float* Yb = Y + (size_t)br * 40 * Cout * 256;
    const int mo = blockIdx.y*64, no = blockIdx.x*128;
    __shared__ __align__(16) float Ws[16][64];
    __shared__ __align__(16) float Xs[16][128];
    const int tid = threadIdx.x;
    const int tx = tid & 15, ty = tid >> 4;
    u64 acc[4][4];
    #pragma unroll
    for (int i = 0; i < 4; i++)
        #pragma unroll
        for (int j = 0; j < 4; j++) acc[i][j] = 0ull;
    const float* Xg = X + (size_t)g*CIN*256;
    for (int k0 = 0; k0 < CIN; k0 += 16) {
        {
            int m = tid >> 2, kq = (tid & 3)*4;
            float4 w4 = *reinterpret_cast<const float4*>(&W[(mo+m)*CIN + k0 + kq]);
            Ws[kq+0][m] = w4.x; Ws[kq+1][m] = w4.y; Ws[kq+2][m] = w4.z; Ws[kq+3][m] = w4.w;
        }
        {
            int kr = tid >> 4, nq = (tid & 15)*8;
            *reinterpret_cast<float4*>(&Xs[kr][nq]) =
                *reinterpret_cast<const float4*>(&Xg[(k0+kr)*256 + no + nq]);
            *reinterpret_cast<float4*>(&Xs[kr][nq+4]) =
                *reinterpret_cast<const float4*>(&Xg[(k0+kr)*256 + no + nq + 4]);
        }
        __syncthreads();
        #pragma unroll
        for (int kk = 0; kk < 16; kk++) {
            u64 a2[4];
            #pragma unroll
            for (int i = 0; i < 4; i++) { float a = Ws[kk][ty*4+i]; PACK2(a2[i], a, a); }
            ulonglong2 bb0 = *reinterpret_cast<const ulonglong2*>(&Xs[kk][tx*8]);
            ulonglong2 bb1 = *reinterpret_cast<const ulonglong2*>(&Xs[kk][tx*8+4]);
            u64 b2[4] = {bb0.x, bb0.y, bb1.x, bb1.y};
            #pragma unroll
            for (int i = 0; i < 4; i++)
                #pragma unroll
                for (int j = 0; j < 4; j++)
                    FMA2(acc[i][j], a2[i], b2[j]);
        }
        __syncthreads();
    }
    #pragma unroll
    for (int i = 0; i < 4; i++) {
        int o = mo + ty*4 + i;
        float gm = bnp[o], bt = bnp[Cout+o], mu = bnp[2*Cout+o], vr = bnp[3*Cout+o];
        float s = gm * rsqrtf(vr + EPSF);
        float off = bt - mu*s + (bias ? s*bias[o] : 0.f);
        u64 s2, o2; PACK2(s2, s, s); PACK2(o2, off, off);
        float r[8];
        #pragma unroll
        for (int j = 0; j < 4; j++) {
            u64 d; FMA2N(d, acc[i][j], s2, o2);
            UNPACK2(r[2*j], r[2*j+1], d);
        }
        float* yp = &Yb[((size_t)g*Cout + o)*256 + no + tx*8];
        *reinterpret_cast<float4*>(yp)   = make_float4(r[0], r[1], r[2], r[3]);
        *reinterpret_cast<float4*>(yp+4) = make_float4(r[4], r[5], r[6], r[7]);
    }
}

// ---------------- GEMM + BN + bias + fused LIF over t, 64x64 tiles (fc1) ----------------
template<int CIN>
__global__ void gemm_lif_kernel(const float* __restrict__ X, const float* __restrict__ W,
                                const float* __restrict__ bnp, const float* __restrict__ bias,
                                float* __restrict__ Y, int Cout) {
    const int b = blockIdx.z;
    const int mo = blockIdx.y*64, no = blockIdx.x*64;
    __shared__ __align__(16) float Ws[16][64];
    __shared__ __align__(16) float Xs[16][64];
    const int tid = threadIdx.x;
    const int tx = tid & 15, ty = tid >> 4;
    float bns[4], bno[4];
    #pragma unroll
    for (int i = 0; i < 4; i++) {
        int o = mo + ty*4 + i;
        float gm = bnp[o], bt = bnp[Cout+o], mu = bnp[2*Cout+o], vr = bnp[3*Cout+o];
        float s = gm * rsqrtf(vr + EPSF);
        bns[i] = s; bno[i] = bt - mu*s + (bias ? s*bias[o] : 0.f);
    }
    float mem[4][4];
    #pragma unroll
    for (int i = 0; i < 4; i++)
        #pragma unroll
        for (int j = 0; j < 4; j++) mem[i][j] = 0.f;

    for (int t = 0; t < 10; t++) {
        const float* Xg = X + ((size_t)(t*4 + b))*CIN*256;
        u64 acc[4][2];
        #pragma unroll
        for (int i = 0; i < 4; i++) { acc[i][0] = 0ull; acc[i][1] = 0ull; }
        for (int k0 = 0; k0 < CIN; k0 += 16) {
            {
                int m = tid >> 2, kq = (tid & 3)*4;
                float4 w4 = *reinterpret_cast<const float4*>(&W[(mo+m)*CIN + k0 + kq]);
                Ws[kq+0][m] = w4.x; Ws[kq+1][m] = w4.y; Ws[kq+2][m] = w4.z; Ws[kq+3][m] = w4.w;
            }
            {
                int kr = tid >> 4, nq = (tid & 15)*4;
                *reinterpret_cast<float4*>(&Xs[kr][nq]) =
                    *reinterpret_cast<const float4*>(&Xg[(k0+kr)*256 + no + nq]);
            }
            __syncthreads();
            #pragma unroll
            for (int kk = 0; kk < 16; kk++) {
                u64 a2[4];
                #pragma unroll
                for (int i = 0; i < 4; i++) { float a = Ws[kk][ty*4+i]; PACK2(a2[i], a, a); }
                ulonglong2 bb = *reinterpret_cast<const ulonglong2*>(&Xs[kk][tx*4]);
                #pragma unroll
                for (int i = 0; i < 4; i++) {
                    FMA2(acc[i][0], a2[i], bb.x);
                    FMA2(acc[i][1], a2[i], bb.y);
                }
            }
            __syncthreads();
        }
        #pragma unroll
        for (int i = 0; i < 4; i++) {
            int o = mo + ty*4 + i;
            float r[4];
            #pragma unroll
            for (int j = 0; j < 2; j++) {
                float lo, hi; UNPACK2(lo, hi, acc[i][j]);
                r[2*j] = bns[i]*lo + bno[i]; r[2*j+1] = bns[i]*hi + bno[i];
            }
            float sp[4];
            #pragma unroll
            for (int j = 0; j < 4; j++) {
                float m2 = mem[i][j] + 0.5f*(r[j] - mem[i][j]);
                float s = m2 > 1.0f ? 1.f : 0.f;
                sp[j] = s;
                mem[i][j] = (s > 0.f) ? 0.f : m2;
            }
            float* yp = &Y[((size_t)(t*4 + b)*Cout + o)*256 + no + tx*4];
            *reinterpret_cast<float4*>(yp) = make_float4(sp[0], sp[1], sp[2], sp[3]);
        }
    }
}

// ---------------- TIM up-conv + bn1 + fused LIF1 -> 40-bit spike masks ------------------
// grid (c=256, b=4, br=3), 256 threads = one (h,w) pixel. Weights in smem (LDS.128),
// f32x2 accumulation. Emits ONE u64 mask per pixel (bit j = spike of channel j).
__global__ void upconv_lif_kernel(const float* __restrict__ A, u64* __restrict__ M) {
    extern __shared__ __align__(16) float sm[];
    float* As  = sm;          // [10][3][18][18] = 9720
    float* Wsm = sm + 9720;   // [270][40]       = 10800
    const int c = blockIdx.x, b = blockIdx.y, br = blockIdx.z;
    const float* Ab = A + (size_t)br * BR_STRIDE_A;
    const int tid = threadIdx.x;
    for (int i = tid; i < 10800; i += 256) Wsm[i] = g_WupT[i];
    for (int idx = tid; idx < 9720; idx += 256) {
        int t = idx / 972, q = idx % 972;
        int dc = q / 324, q2 = q % 324;
        int hh = q2 / 18, ww = q2 % 18;
        int cc = c - 1 + dc;
        float v = 0.f;
        if (cc >= 0 && cc < 256 && hh >= 1 && hh <= 16 && ww >= 1 && ww <= 16)
            v = Ab[((t*4 + b)*256 + cc)*256 + (hh-1)*16 + (ww-1)];
        As[idx] = v;
    }
    __syncthreads();
    const int h = tid >> 4, w = tid & 15;
    u64 acc[20];
    #pragma unroll
    for (int j = 0; j < 20; j++) acc[j] = 0ull;
    for (int t = 0; t < 10; t++) {
        const float* at = As + t*972 + h*18 + w;
        const u64* wt = reinterpret_cast<const u64*>(Wsm) + t*540;
        #pragma unroll
        for (int dc = 0; dc < 3; dc++)
            #pragma unroll
            for (int dh = 0; dh < 3; dh++)
                #pragma unroll
                for (int dw = 0; dw < 3; dw++) {
                    float a = at[dc*324 + dh*18 + dw];
                    u64 a2; PACK2(a2, a, a);
                    const ulonglong2* wp2 =
                        reinterpret_cast<const ulonglong2*>(wt + (dc*9 + dh*3 + dw)*20);
                    #pragma unroll
                    for (int j2 = 0; j2 < 10; j2++) {
                        ulonglong2 wv = wp2[j2];
                        FMA2(acc[2*j2  ], a2, wv.x);
                        FMA2(acc[2*j2+1], a2, wv.y);
                    }
                }
    }
    float av[40];
    #pragma unroll
    for (int p = 0; p < 20; p++) {
        float lo, hi; UNPACK2(lo, hi, acc[p]);
        av[2*p] = lo; av[2*p+1] = hi;
    }
    // fused LIF1: scan s over j = 4s+q, membrane per q; pack spikes into 40-bit mask
    u64 mask = 0ull;
    #pragma unroll
    for (int q = 0; q < 4; q++) {
        float memv = 0.f;
        #pragma unroll
        for (int s = 0; s < 10; s++) {
            int j = 4*s + q;
            float x = g_bn1s[j]*av[j] + g_bn1o[j];
            memv += 0.5f*(x - memv);
            if (memv > 1.0f) { mask |= (1ull << j); memv = 0.f; }
        }
    }
    M[((size_t)(br*4 + b)*256 + c)*256 + tid] = mask;
}

// ---------------- TIM down-conv from spike masks + bn2 + fused LIF2 ---------------------
// grid (c=256, b=4, br=3), 256 threads. Single coalesced fill of 972 masks, one sync.
// Per-tap group sums via 16-entry nibble LUT (27 taps x 10 t), exact partial sums.
__global__ void downconv_lif_kernel(const u64* __restrict__ Mg, const float* __restrict__ Wd_g,
                                    const float* __restrict__ bn2, float* __restrict__ Out) {
    const int c = blockIdx.x, b = blockIdx.y, br = blockIdx.z;
    const u64* Mb = Mg + (size_t)(br*4 + b)*65536;
    float* Ob = Out + (size_t)br * BR_STRIDE_A;
    __shared__ __align__(16) u64 Ms[972];       // [dc=3][18][18] masks
    __shared__ float LUT[4320];                 // [tap=27][t=10][nib=16]
    __shared__ float s_sc[10], s_of[10];
    const int tid = threadIdx.x;
    // LUT: partial sums of the 4 r-weights selected by nibble
    for (int i = tid; i < 4320; i += 256) {
        int tap = i / 160, rem = i - tap*160;
        int t = rem >> 4, nib = rem & 15;
        float v = 0.f;
        if (nib & 1) v += Wd_g[t*108 +  0 + tap];
        if (nib & 2) v += Wd_g[t*108 + 27 + tap];
        if (nib & 4) v += Wd_g[t*108 + 54 + tap];
        if (nib & 8) v += Wd_g[t*108 + 81 + tap];
        LUT[i] = v;
    }
    if (tid < 10) {
        float gm = bn2[tid], bt = bn2[10+tid], mu = bn2[20+tid], vr = bn2[30+tid];
        float s = gm * rsqrtf(vr + EPSF);
        s_sc[tid] = s; s_of[tid] = bt - mu*s;
    }
    // fill halo masks (zero padded)
    for (int i = tid; i < 972; i += 256) {
        int dc = i / 324, rem = i - dc*324;
        int hh = rem / 18, ww = rem - hh*18;
        int cc = c - 1 + dc;
        u64 m = 0ull;
        if (cc >= 0 && cc < 256 && hh >= 1 && hh <= 16 && ww >= 1 && ww <= 16)
            m = Mb[cc*256 + (hh-1)*16 + (ww-1)];
        Ms[i] = m;
    }
    __syncthreads();
    const int h = tid >> 4, w = tid & 15;
    float acc[10];
    #pragma unroll
    for (int t = 0; t < 10; t++) acc[t] = 0.f;
    #pragma unroll
    for (int dc = 0; dc < 3; dc++)
        #pragma unroll
        for (int dh = 0; dh < 3; dh++)
            #pragma unroll
            for (int dw = 0; dw < 3; dw++) {
                u64 m = Ms[dc*324 + (h+dh)*18 + (w+dw)];
                unsigned mlo = (unsigned)m, mhi = (unsigned)(m >> 32);
                const float* lt = LUT + (dc*9 + dh*3 + dw)*160;
                #pragma unroll
                for (int t = 0; t < 8; t++)
                    acc[t] += lt[t*16 + ((mlo >> (4*t)) & 15u)];
                acc[8] += lt[128 + (mhi & 15u)];
                acc[9] += lt[144 + ((mhi >> 4) & 15u)];
            }
    // fused LIF2 over t
    float memv = 0.f;
    #pragma unroll
    for (int t = 0; t < 10; t++) {
        float x = s_sc[t]*acc[t] + s_of[t];
        memv += 0.5f*(x - memv);
        float sp = memv > 1.0f ? 1.f : 0.f;
        Ob[(t*4 + b)*65536 + c*256 + tid] = sp;
        if (sp > 0.f) memv = 0.f;
    }
}

// ---------------- attention via G = K^T V (exact for binary spikes), per (h,b,t) --------
__global__ void attn_kernel(const float* __restrict__ Qp, const float* __restrict__ Kp,
                            const float* __restrict__ Vp, float* __restrict__ Op) {
    const int hh = blockIdx.x, b = blockIdx.y, t = blockIdx.z;
    __shared__ __align__(16) float Ks[256*17];
    __shared__ __align__(16) float Vs[256*17];
    __shared__ __align__(16) float Gs[16*18];
    const int tid = threadIdx.x;
    const int base = (t*4 + b)*65536 + hh*4096;
    for (int idx = tid; idx < 4096; idx += 256) {
        int dd = idx >> 8, m = idx & 255;
        Ks[m*17 + dd] = Kp[base + dd*256 + m];
        Vs[m*17 + dd] = Vp[base + dd*256 + m];
    }
    __syncthreads();
    const int d1 = tid >> 4, d2 = tid & 15;
    float g = 0.f;
    #pragma unroll 8
    for (int m = 0; m < 256; m++)
        g += Ks[m*17 + d1] * Vs[m*17 + d2];
    Gs[d1*18 + d2] = g;
    __syncthreads();
    const int n = tid;
    u64 o2[8];
    #pragma unroll
    for (int i = 0; i < 8; i++) o2[i] = 0ull;
    #pragma unroll
    for (int dd1 = 0; dd1 < 16; dd1++) {
        float q = Qp[base + dd1*256 + n];
        u64 q2; PACK2(q2, q, q);
        const u64* gp = reinterpret_cast<const u64*>(&Gs[dd1*18]);
        #pragma unroll
        for (int i = 0; i < 8; i++) FMA2(o2[i], q2, gp[i]);
    }
    #pragma unroll
    for (int i = 0; i < 8; i++) {
        float lo, hi; UNPACK2(lo, hi, o2[i]);
        Op[base + (2*i  )*256 + n] = 0.25f*lo;
        Op[base + (2*i+1)*256 + n] = 0.25f*hi;
    }
}

// ---------------- standard LIF over leading T dim, layout (t,b,C,n); optional residual ----
__global__ void lif_std_kernel(const float* __restrict__ in, float* __restrict__ out,
                               const float* __restrict__ res, int Cch, float vth) {
    int idx = blockIdx.x*256 + threadIdx.x;
    int per_b = Cch*256;
    int b = idx / per_b, cn = idx - b*per_b;
    float mem = 0.f;
    #pragma unroll
    for (int t = 0; t < 10; t++) {
        int off = (t*4 + b)*per_b + cn;
        float x = in[off];
        mem += 0.5f*(x - mem);
        float sp = mem > vth ? 1.f : 0.f;
        out[off] = res ? res[off] + sp : sp;
        if (sp > 0.f) mem = 0.f;
    }
}

// ---------------- launch ----------------
extern "C" void kernel_launch(void* const* d_in, const int* in_sizes, int n_in,
                              void* d_out, int out_size) {
    const float* x        = (const float*)d_in[0];
    const float* q_w      = (const float*)d_in[1];
    const float* q_bn     = (const float*)d_in[2];
    const float* k_w      = (const float*)d_in[3];
    const float* k_bn     = (const float*)d_in[4];
    const float* v_w      = (const float*)d_in[5];
    const float* v_bn     = (const float*)d_in[6];
    const float* proj_w   = (const float*)d_in[7];
    const float* proj_bn  = (const float*)d_in[8];
    const float* tim_up_w = (const float*)d_in[9];
    const float* tim_bn1  = (const float*)d_in[10];
    const float* tim_dn_w = (const float*)d_in[11];
    const float* tim_bn2  = (const float*)d_in[12];
    const float* fc1_w    = (const float*)d_in[13];
    const float* fc1_b    = (const float*)d_in[14];
    const float* fc1_bn   = (const float*)d_in[15];
    const float* fc2_w    = (const float*)d_in[16];
    const float* fc2_b    = (const float*)d_in[17];
    const float* fc2_bn   = (const float*)d_in[18];
    float* out = (float*)d_out;

    float *bA,*bQKV,*bO,*bSpO,*bP,*bH,*bS2,*bF2;
    u64 *bM;
    cudaGetSymbolAddress((void**)&bA,   g_A);
    cudaGetSymbolAddress((void**)&bM,   g_M);
    cudaGetSymbolAddress((void**)&bQKV, g_QKV);
    cudaGetSymbolAddress((void**)&bO,   g_O);
    cudaGetSymbolAddress((void**)&bSpO, g_SpO);
    cudaGetSymbolAddress((void**)&bP,   g_P);
    cudaGetSymbolAddress((void**)&bH,   g_H);
    cudaGetSymbolAddress((void**)&bS2,  g_S2);
    cudaGetSymbolAddress((void**)&bF2,  g_F2);

    cudaFuncSetAttribute(upconv_lif_kernel, cudaFuncAttributeMaxDynamicSharedMemorySize, 82080);

    prep_kernel<<<43, 256>>>(tim_up_w, tim_bn1);

    // --- q/k/v branches, fused TIM pipeline (spike masks between convs) ---
    gemm_bn_kernel<256><<<dim3(2,4,120), 256>>>(x, q_w, k_w, v_w, q_bn, k_bn, v_bn,
                                                nullptr, bA, 256);
    upconv_lif_kernel<<<dim3(256,4,3), 256, 82080>>>(bA, bM);
    downconv_lif_kernel<<<dim3(256,4,3), 256>>>(bM, tim_dn_w, tim_bn2, bQKV);

    // --- attention (G-trick, exact), then attn-LIF ---
    attn_kernel<<<dim3(16,4,10), 256>>>(bQKV, bQKV + BR_STRIDE_A, bQKV + 2*BR_STRIDE_A, bO);
    lif_std_kernel<<<1024, 256>>>(bO, bSpO, nullptr, 256, 0.5f);

    // --- proj + residual ---
    gemm_bn_kernel<256><<<dim3(2,4,40), 256>>>(bSpO, proj_w, proj_w, proj_w,
                                               proj_bn, proj_bn, proj_bn, nullptr, bP, 256);
    lif_std_kernel<<<1024, 256>>>(bP, bH, x, 256, 1.0f);   // h = x + ssa

    // --- mlp: fc1 fused with LIF (64x64 tiles); fc2 + final LIF with residual ---
    gemm_lif_kernel<256><<<dim3(4,16,4), 256>>>(bH, fc1_w, fc1_bn, fc1_b, bS2, 1024);
    gemm_bn_kernel<1024><<<dim3(2,4,40), 256>>>(bS2, fc2_w, fc2_w, fc2_w,
                                                fc2_bn, fc2_bn, fc2_bn, fc2_b, bF2, 256);
    lif_std_kernel<<<1024, 256>>>(bF2, out, bH, 256, 1.0f);
}

// round 13
// speedup vs baseline: 2.7394x; 1.4421x over previous
#include <cuda_runtime.h>
#include <cuda_bf16.h>
#include <cstdint>

#define TT 10
#define BB 4
#define CCH 256
#define NPIX 256
#define HIDN 1024
#define TRJ 40
#define EPSF 1e-5f

typedef unsigned long long u64;
typedef __nv_bfloat16 bf16;

#define FMA2(d,a,b)    asm("fma.rn.f32x2 %0, %1, %2, %0;" : "+l"(d) : "l"(a), "l"(b))
#define PACK2(d,lo,hi) asm("mov.b64 %0, {%1, %2};" : "=l"(d) : "f"(lo), "f"(hi))
#define UNPACK2(lo,hi,s) asm("mov.b64 {%0, %1}, %2;" : "=f"(lo), "=f"(hi) : "l"(s))

#define BR_STRIDE_A  2621440

// ---------------- mma.sync helpers (sm_80+ PTX, works on plain sm_103 target) ----------
__device__ __forceinline__ uint32_t smem_to_u32(const void* p) {
    uint32_t a;
    asm("{ .reg .u64 t; cvta.to.shared.u64 t, %1; cvt.u32.u64 %0, t; }" : "=r"(a) : "l"(p));
    return a;
}
#define LDSM4(r, addr) \
    asm volatile("ldmatrix.sync.aligned.m8n8.x4.shared.b16 {%0,%1,%2,%3}, [%4];" \
        : "=r"((r)[0]), "=r"((r)[1]), "=r"((r)[2]), "=r"((r)[3]) : "r"(addr))
#define MMA16816(c, a, b0v, b1v) \
    asm volatile("mma.sync.aligned.m16n8k16.row.col.f32.bf16.bf16.f32 " \
        "{%0,%1,%2,%3}, {%4,%5,%6,%7}, {%8,%9}, {%0,%1,%2,%3};" \
        : "+f"((c)[0]), "+f"((c)[1]), "+f"((c)[2]), "+f"((c)[3]) \
        : "r"((a)[0]), "r"((a)[1]), "r"((a)[2]), "r"((a)[3]), "r"(b0v), "r"(b1v))

// ---------------- scratch ----------------
__device__ float g_A  [3*TT*BB*CCH*NPIX];
__device__ u64   g_M  [3*BB*CCH*NPIX];
__device__ float g_QKV[3*TT*BB*CCH*NPIX];
__device__ float g_O  [TT*BB*CCH*NPIX];
__device__ float g_P  [TT*BB*CCH*NPIX];
__device__ float g_H  [TT*BB*CCH*NPIX];
__device__ float g_F1 [TT*BB*HIDN*NPIX];
__device__ float g_F2 [TT*BB*CCH*NPIX];
__device__ float g_WupT[270*40];
__device__ float g_bn1s[40], g_bn1o[40];
// bf16 limbs
__device__ bf16 g_Wq_h[196608], g_Wq_m[196608], g_Wq_l[196608];
__device__ bf16 g_Wp_h[65536],  g_Wp_m[65536],  g_Wp_l[65536];
__device__ bf16 g_W1_h[262144], g_W1_m[262144], g_W1_l[262144];
__device__ bf16 g_W2_h[262144], g_W2_m[262144], g_W2_l[262144];
__device__ bf16 g_Xt_h[2621440], g_Xt_m[2621440], g_Xt_l[2621440];
__device__ bf16 g_Ht_h[2621440], g_Ht_m[2621440], g_Ht_l[2621440];
__device__ bf16 g_SpOt[2621440];     // binary, [g][n][256]
__device__ bf16 g_S2t[10485760];     // binary, [g][n][1024]

__device__ __forceinline__ void split3(float v, bf16& h, bf16& m, bf16& l) {
    h = __float2bfloat16(v);
    float r1 = v - __bfloat162float(h);
    m = __float2bfloat16(r1);
    l = __float2bfloat16(r1 - __bfloat162float(m));
}

// ---------------- prep ----------------
__global__ void prep_kernel(const float* __restrict__ up_w, const float* __restrict__ bn1) {
    for (int idx = blockIdx.x*blockDim.x + threadIdx.x; idx < 10800;
         idx += gridDim.x*blockDim.x) {
        int j = idx / 270, r = idx % 270;
        g_WupT[r*40 + j] = up_w[idx];
    }
    int i = blockIdx.x*blockDim.x + threadIdx.x;
    if (i < 40) {
        float gm = bn1[i], bt = bn1[40+i], mu = bn1[80+i], vr = bn1[120+i];
        float s = gm * rsqrtf(vr + EPSF);
        g_bn1s[i] = s; g_bn1o[i] = bt - mu*s;
    }
}

__global__ void prep_w_kernel(const float* __restrict__ q_w, const float* __restrict__ k_w,
                              const float* __restrict__ v_w, const float* __restrict__ proj_w,
                              const float* __restrict__ fc1_w, const float* __restrict__ fc2_w) {
    int i = blockIdx.x*256 + threadIdx.x;
    if (i >= 786432) return;
    float v; bf16 *dh, *dm, *dl; int o;
    if (i < 196608) {
        int br = i >> 16;
        const float* w = (br == 0) ? q_w : ((br == 1) ? k_w : v_w);
        v = w[i & 65535]; o = i; dh = g_Wq_h; dm = g_Wq_m; dl = g_Wq_l;
    } else if (i < 262144) {
        o = i - 196608; v = proj_w[o]; dh = g_Wp_h; dm = g_Wp_m; dl = g_Wp_l;
    } else if (i < 524288) {
        o = i - 262144; v = fc1_w[o]; dh = g_W1_h; dm = g_W1_m; dl = g_W1_l;
    } else {
        o = i - 524288; v = fc2_w[o]; dh = g_W2_h; dm = g_W2_m; dl = g_W2_l;
    }
    bf16 h, m, l; split3(v, h, m, l);
    dh[o] = h; dm[o] = m; dl[o] = l;
}

// float [g][256][256] -> transposed 3-limb bf16 [g][n][256]
__global__ void cvt_xt_kernel(const float* __restrict__ X, bf16* __restrict__ Xh,
                              bf16* __restrict__ Xm, bf16* __restrict__ Xl) {
    __shared__ float s[32][33];
    const int c0 = blockIdx.x*32, n0 = blockIdx.y*32, g = blockIdx.z;
    const int tid = threadIdx.x;
    #pragma unroll
    for (int it = 0; it < 4; it++) {
        int c = (tid>>5) + it*8;
        s[c][tid&31] = X[((size_t)g*256 + c0+c)*256 + n0 + (tid&31)];
    }
    __syncthreads();
    const int cc = tid & 31;
    #pragma unroll
    for (int it = 0; it < 4; it++) {
        int nn = (tid>>5) + it*8;
        bf16 h, m, l; split3(s[cc][nn], h, m, l);
        size_t o = ((size_t)g*256 + n0+nn)*256 + c0+cc;
        Xh[o] = h; Xm[o] = m; Xl[o] = l;
    }
}

// LIF over t + transpose to binary bf16 [g][n][C]
__global__ void lif_t_bf16_kernel(const float* __restrict__ in, bf16* __restrict__ out,
                                  int C, float vth) {
    __shared__ float s[10][32][33];
    const int c0 = blockIdx.x*32, n0 = blockIdx.y*32, b = blockIdx.z;
    const int tid = threadIdx.x;
    for (int t = 0; t < 10; t++)
        #pragma unroll
        for (int it = 0; it < 4; it++) {
            int c = (tid>>5) + it*8;
            s[t][c][tid&31] = in[((size_t)(t*4+b)*C + c0+c)*256 + n0 + (tid&31)];
        }
    __syncthreads();
    const int cc = tid & 31;
    #pragma unroll
    for (int pass = 0; pass < 4; pass++) {
        int nn = (tid>>5) + pass*8;
        float memv = 0.f;
        #pragma unroll
        for (int t = 0; t < 10; t++) {
            float x = s[t][cc][nn];
            memv += 0.5f*(x - memv);
            float sp = memv > vth ? 1.f : 0.f;
            out[((size_t)(t*4+b)*256 + n0+nn)*C + c0+cc] = __float2bfloat16(sp);
            if (sp > 0.f) memv = 0.f;
        }
    }
}

// ---------------- mma.sync GEMM + BN(+bias), limb-decomposed --------------------------
// D[mo+m][no+n] = sum_k W[m][k]*X[n][k]. W: 3 limbs; X: NB limbs (3 -> 6 products,
// 1 -> 3 products). Tile M=128 N=64, K chunks of 64, 8 warps (warp = 16 rows).
// grid (nx=4, my=Cout/128, z=nbr*40). smem: A 3*16KB @0, B NB*8KB @49152.
template<int CIN, int NB>
__global__ void __launch_bounds__(256) gemm_mma_kernel(
        const bf16* __restrict__ Xh, const bf16* __restrict__ Xm, const bf16* __restrict__ Xl,
        const bf16* __restrict__ Wh, const bf16* __restrict__ Wm, const bf16* __restrict__ Wl,
        const float* __restrict__ B0, const float* __restrict__ B1, const float* __restrict__ B2,
        const float* __restrict__ bias, float* __restrict__ Y, int Cout) {
    extern __shared__ char dsm[];
    const int z = blockIdx.z, br = z/40, g = z - br*40;
    const int mo = blockIdx.y*128, no = blockIdx.x*64;
    const int tid = threadIdx.x, wid = tid>>5, lane = tid&31;
    const bf16* Wp[3] = {Wh + (size_t)br*Cout*CIN, Wm + (size_t)br*Cout*CIN,
                         Wl + (size_t)br*Cout*CIN};
    const bf16* Xp[3];
    Xp[0] = Xh + (size_t)g*256*CIN;
    Xp[1] = (NB > 1) ? Xm + (size_t)g*256*CIN : Xp[0];
    Xp[2] = (NB > 1) ? Xl + (size_t)g*256*CIN : Xp[0];

    float acc[8][4];
    #pragma unroll
    for (int j = 0; j < 8; j++)
        #pragma unroll
        for (int i = 0; i < 4; i++) acc[j][i] = 0.f;

    const uint32_t sbase = smem_to_u32(dsm);
    // A lane mapping: lanes 0-7 rows R+0..7 @k, 8-15 rows R+8..15 @k,
    //                 16-23 rows R+0..7 @k+16B, 24-31 rows R+8..15 @k+16B
    const int rowA = wid*16 + (lane & 7) + ((lane & 8) ? 8 : 0);
    const int h16A = (lane & 16) ? 16 : 0;
    const int axor = (rowA & 7)*16;
    const uint32_t aoff = sbase + rowA*128;
    // B lane mapping (x4 covers nblk pair): 0-7 rows j16+0..7 @k, 8-15 same rows @k+16B,
    //                 16-23 rows j16+8..15 @k, 24-31 rows +8 @k+16B
    const int rB = (lane & 7) + ((lane & 16) ? 8 : 0);
    const int h16B = (lane & 8) ? 16 : 0;
    const int bxor = (lane & 7)*16;
    const uint32_t boff = sbase + 49152 + rB*128;

    for (int ch = 0; ch < CIN/64; ch++) {
        #pragma unroll
        for (int l = 0; l < 3; l++) {         // A = W limbs, 128x64 bf16 each
            #pragma unroll
            for (int it = 0; it < 4; it++) {
                int q = tid + it*256;
                int row = q >> 3, c16 = q & 7;
                uint4 v = *reinterpret_cast<const uint4*>(
                    &Wp[l][(size_t)(mo+row)*CIN + ch*64 + c16*8]);
                *reinterpret_cast<uint4*>(dsm + l*16384 + row*128 +
                                          ((c16*16) ^ ((row & 7)*16))) = v;
            }
        }
        #pragma unroll
        for (int l = 0; l < NB; l++) {        // B = X limbs, 64x64 bf16 each
            #pragma unroll
            for (int it = 0; it < 2; it++) {
                int q = tid + it*256;
                int row = q >> 3, c16 = q & 7;
                uint4 v = *reinterpret_cast<const uint4*>(
                    &Xp[l][(size_t)(no+row)*CIN + ch*64 + c16*8]);
                *reinterpret_cast<uint4*>(dsm + 49152 + l*8192 + row*128 +
                                          ((c16*16) ^ ((row & 7)*16))) = v;
            }
        }
        __syncthreads();
        #pragma unroll
        for (int ks = 0; ks < 4; ks++) {
            uint32_t af[3][4];
            #pragma unroll
            for (int la = 0; la < 3; la++)
                LDSM4(af[la], aoff + la*16384 + ((ks*32 + h16A) ^ axor));
            #pragma unroll
            for (int j = 0; j < 4; j++) {
                #pragma unroll
                for (int lb = 0; lb < NB; lb++) {
                    uint32_t bf4[4];
                    LDSM4(bf4, boff + lb*8192 + j*2048 + ((ks*32 + h16B) ^ bxor));
                    // limb-order cutoff: NB==3 -> la+lb<=2 (6 products); NB==1 -> all 3
                    const int lamax = (NB == 3) ? (3 - lb) : 3;
                    #pragma unroll
                    for (int la = 0; la < 3; la++) {
                        if (la < lamax) {
                            MMA16816(acc[2*j],   af[la], bf4[0], bf4[1]);
                            MMA16816(acc[2*j+1], af[la], bf4[2], bf4[3]);
                        }
                    }
                }
            }
        }
        __syncthreads();
    }
    // epilogue: BN (+bias)
    const float* bnp = (br == 0) ? B0 : ((br == 1) ? B1 : B2);
    const int g4 = lane >> 2, tg = lane & 3;
    const int o0 = mo + wid*16 + g4, o1 = o0 + 8;
    float gm0 = bnp[o0], bt0 = bnp[Cout+o0], mu0 = bnp[2*Cout+o0], vr0 = bnp[3*Cout+o0];
    float s0 = gm0 * rsqrtf(vr0 + EPSF);
    float f0 = bt0 - mu0*s0 + (bias ? s0*bias[o0] : 0.f);
    float gm1 = bnp[o1], bt1 = bnp[Cout+o1], mu1 = bnp[2*Cout+o1], vr1 = bnp[3*Cout+o1];
    float s1 = gm1 * rsqrtf(vr1 + EPSF);
    float f1 = bt1 - mu1*s1 + (bias ? s1*bias[o1] : 0.f);
    float* Yb = Y + ((size_t)(br*40 + g)*Cout)*256;
    #pragma unroll
    for (int j = 0; j < 8; j++) {
        int col = no + j*8 + tg*2;
        float2 r0; r0.x = s0*acc[j][0] + f0; r0.y = s0*acc[j][1] + f0;
        *reinterpret_cast<float2*>(&Yb[(size_t)o0*256 + col]) = r0;
        float2 r1; r1.x = s1*acc[j][2] + f1; r1.y = s1*acc[j][3] + f1;
        *reinterpret_cast<float2*>(&Yb[(size_t)o1*256 + col]) = r1;
    }
}

// ---------------- TIM up-conv + bn1 + LIF1 -> 40-bit masks ------------------------------
__global__ void upconv_lif_kernel(const float* __restrict__ A, u64* __restrict__ M) {
    extern __shared__ __align__(16) float sm[];
    float* As  = sm;
    float* Wsm = sm + 9720;
    const int c = blockIdx.x, b = blockIdx.y, br = blockIdx.z;
    const float* Ab = A + (size_t)br * BR_STRIDE_A;
    const int tid = threadIdx.x;
    for (int i = tid; i < 10800; i += 256) Wsm[i] = g_WupT[i];
    for (int idx = tid; idx < 9720; idx += 256) {
        int t = idx / 972, q = idx % 972;
        int dc = q / 324, q2 = q % 324;
        int hh = q2 / 18, ww = q2 % 18;
        int cc = c - 1 + dc;
        float v = 0.f;
        if (cc >= 0 && cc < 256 && hh >= 1 && hh <= 16 && ww >= 1 && ww <= 16)
            v = Ab[((t*4 + b)*256 + cc)*256 + (hh-1)*16 + (ww-1)];
        As[idx] = v;
    }
    __syncthreads();
    const int h = tid >> 4, w = tid & 15;
    u64 acc[20];
    #pragma unroll
    for (int j = 0; j < 20; j++) acc[j] = 0ull;
    for (int t = 0; t < 10; t++) {
        const float* at = As + t*972 + h*18 + w;
        const u64* wt = reinterpret_cast<const u64*>(Wsm) + t*540;
        #pragma unroll
        for (int dc = 0; dc < 3; dc++)
            #pragma unroll
            for (int dh = 0; dh < 3; dh++)
                #pragma unroll
                for (int dw = 0; dw < 3; dw++) {
                    float a = at[dc*324 + dh*18 + dw];
                    u64 a2; PACK2(a2, a, a);
                    const ulonglong2* wp2 =
                        reinterpret_cast<const ulonglong2*>(wt + (dc*9 + dh*3 + dw)*20);
                    #pragma unroll
                    for (int j2 = 0; j2 < 10; j2++) {
                        ulonglong2 wv = wp2[j2];
                        FMA2(acc[2*j2  ], a2, wv.x);
                        FMA2(acc[2*j2+1], a2, wv.y);
                    }
                }
    }
    float av[40];
    #pragma unroll
    for (int p = 0; p < 20; p++) {
        float lo, hi; UNPACK2(lo, hi, acc[p]);
        av[2*p] = lo; av[2*p+1] = hi;
    }
    u64 mask = 0ull;
    #pragma unroll
    for (int q = 0; q < 4; q++) {
        float memv = 0.f;
        #pragma unroll
        for (int s = 0; s < 10; s++) {
            int j = 4*s + q;
            float x = g_bn1s[j]*av[j] + g_bn1o[j];
            memv += 0.5f*(x - memv);
            if (memv > 1.0f) { mask |= (1ull << j); memv = 0.f; }
        }
    }
    M[((size_t)(br*4 + b)*256 + c)*256 + tid] = mask;
}

// ---------------- TIM down-conv nibble-LUT + bn2 + LIF2 ---------------------------------
__global__ void downconv_lif_kernel(const u64* __restrict__ Mg, const float* __restrict__ Wd_g,
                                    const float* __restrict__ bn2, float* __restrict__ Out) {
    const int c = blockIdx.x, b = blockIdx.y, br = blockIdx.z;
    const u64* Mb = Mg + (size_t)(br*4 + b)*65536;
    float* Ob = Out + (size_t)br * BR_STRIDE_A;
    __shared__ __align__(16) u64 Ms[972];
    __shared__ float LUT[4320];
    __shared__ float s_sc[10], s_of[10];
    const int tid = threadIdx.x;
    for (int i = tid; i < 4320; i += 256) {
        int tap = i / 160, rem = i - tap*160;
        int t = rem >> 4, nib = rem & 15;
        float v = 0.f;
        if (nib & 1) v += Wd_g[t*108 +  0 + tap];
        if (nib & 2) v += Wd_g[t*108 + 27 + tap];
        if (nib & 4) v += Wd_g[t*108 + 54 + tap];
        if (nib & 8) v += Wd_g[t*108 + 81 + tap];
        LUT[i] = v;
    }
    if (tid < 10) {
        float gm = bn2[tid], bt = bn2[10+tid], mu = bn2[20+tid], vr = bn2[30+tid];
        float s = gm * rsqrtf(vr + EPSF);
        s_sc[tid] = s; s_of[tid] = bt - mu*s;
    }
    for (int i = tid; i < 972; i += 256) {
        int dc = i / 324, rem = i - dc*324;
        int hh = rem / 18, ww = rem - hh*18;
        int cc = c - 1 + dc;
        u64 m = 0ull;
        if (cc >= 0 && cc < 256 && hh >= 1 && hh <= 16 && ww >= 1 && ww <= 16)
            m = Mb[cc*256 + (hh-1)*16 + (ww-1)];
        Ms[i] = m;
    }
    __syncthreads();
    const int h = tid >> 4, w = tid & 15;
    float acc[10];
    #pragma unroll
    for (int t = 0; t < 10; t++) acc[t] = 0.f;
    #pragma unroll
    for (int dc = 0; dc < 3; dc++)
        #pragma unroll
        for (int dh = 0; dh < 3; dh++)
            #pragma unroll
            for (int dw = 0; dw < 3; dw++) {
                u64 m = Ms[dc*324 + (h+dh)*18 + (w+dw)];
                unsigned mlo = (unsigned)m, mhi = (unsigned)(m >> 32);
                const float* lt = LUT + (dc*9 + dh*3 + dw)*160;
                #pragma unroll
                for (int t = 0; t < 8; t++)
                    acc[t] += lt[t*16 + ((mlo >> (4*t)) & 15u)];
                acc[8] += lt[128 + (mhi & 15u)];
                acc[9] += lt[144 + ((mhi >> 4) & 15u)];
            }
    float memv = 0.f;
    #pragma unroll
    for (int t = 0; t < 10; t++) {
        float x = s_sc[t]*acc[t] + s_of[t];
        memv += 0.5f*(x - memv);
        float sp = memv > 1.0f ? 1.f : 0.f;
        Ob[(t*4 + b)*65536 + c*256 + tid] = sp;
        if (sp > 0.f) memv = 0.f;
    }
}

// ---------------- attention G = K^T V (exact for binary spikes) -------------------------
__global__ void attn_kernel(const float* __restrict__ Qp, const float* __restrict__ Kp,
                            const float* __restrict__ Vp, float* __restrict__ Op) {
    const int hh = blockIdx.x, b = blockIdx.y, t = blockIdx.z;
    __shared__ __align__(16) float Ks[256*17];
    __shared__ __align__(16) float Vs[256*17];
    __shared__ __align__(16) float Gs[16*18];
    const int tid = threadIdx.x;
    const int base = (t*4 + b)*65536 + hh*4096;
    for (int idx = tid; idx < 4096; idx += 256) {
        int dd = idx >> 8, m = idx & 255;
        Ks[m*17 + dd] = Kp[base + dd*256 + m];
        Vs[m*17 + dd] = Vp[base + dd*256 + m];
    }
    __syncthreads();
    const int d1 = tid >> 4, d2 = tid & 15;
    float g = 0.f;
    #pragma unroll 8
    for (int m = 0; m < 256; m++)
        g += Ks[m*17 + d1] * Vs[m*17 + d2];
    Gs[d1*18 + d2] = g;
    __syncthreads();
    const int n = tid;
    u64 o2[8];
    #pragma unroll
    for (int i = 0; i < 8; i++) o2[i] = 0ull;
    #pragma unroll
    for (int dd1 = 0; dd1 < 16; dd1++) {
        float q = Qp[base + dd1*256 + n];
        u64 q2; PACK2(q2, q, q);
        const u64* gp = reinterpret_cast<const u64*>(&Gs[dd1*18]);
        #pragma unroll
        for (int i = 0; i < 8; i++) FMA2(o2[i], q2, gp[i]);
    }
    #pragma unroll
    for (int i = 0; i < 8; i++) {
        float lo, hi; UNPACK2(lo, hi, o2[i]);
        Op[base + (2*i  )*256 + n] = 0.25f*lo;
        Op[base + (2*i+1)*256 + n] = 0.25f*hi;
    }
}

// ---------------- float LIF over t ------------------------------------------------------
__global__ void lif_std_kernel(const float* __restrict__ in, float* __restrict__ out,
                               const float* __restrict__ res, int Cch, float vth) {
    int idx = blockIdx.x*256 + threadIdx.x;
    int per_b = Cch*256;
    int b = idx / per_b, cn = idx - b*per_b;
    float mem = 0.f;
    #pragma unroll
    for (int t = 0; t < 10; t++) {
        int off = (t*4 + b)*per_b + cn;
        float x = in[off];
        mem += 0.5f*(x - mem);
        float sp = mem > vth ? 1.f : 0.f;
        out[off] = res ? res[off] + sp : sp;
        if (sp > 0.f) mem = 0.f;
    }
}

// ---------------- launch ----------------
extern "C" void kernel_launch(void* const* d_in, const int* in_sizes, int n_in,
                              void* d_out, int out_size) {
    const float* x        = (const float*)d_in[0];
    const float* q_w      = (const float*)d_in[1];
    const float* q_bn     = (const float*)d_in[2];
    const float* k_w      = (const float*)d_in[3];
    const float* k_bn     = (const float*)d_in[4];
    const float* v_w      = (const float*)d_in[5];
    const float* v_bn     = (const float*)d_in[6];
    const float* proj_w   = (const float*)d_in[7];
    const float* proj_bn  = (const float*)d_in[8];
    const float* tim_up_w = (const float*)d_in[9];
    const float* tim_bn1  = (const float*)d_in[10];
    const float* tim_dn_w = (const float*)d_in[11];
    const float* tim_bn2  = (const float*)d_in[12];
    const float* fc1_w    = (const float*)d_in[13];
    const float* fc1_b    = (const float*)d_in[14];
    const float* fc1_bn   = (const float*)d_in[15];
    const float* fc2_w    = (const float*)d_in[16];
    const float* fc2_b    = (const float*)d_in[17];
    const float* fc2_bn   = (const float*)d_in[18];
    float* out = (float*)d_out;

    float *bA,*bQKV,*bO,*bP,*bH,*bF1,*bF2;
    u64 *bM;
    bf16 *bXh,*bXm,*bXl,*bHh,*bHm,*bHl,*bSpOt,*bS2t;
    bf16 *wqh,*wqm,*wql,*wph,*wpm,*wpl,*w1h,*w1m,*w1l,*w2h,*w2m,*w2l;
    cudaGetSymbolAddress((void**)&bA,   g_A);
    cudaGetSymbolAddress((void**)&bM,   g_M);
    cudaGetSymbolAddress((void**)&bQKV, g_QKV);
    cudaGetSymbolAddress((void**)&bO,   g_O);
    cudaGetSymbolAddress((void**)&bP,   g_P);
    cudaGetSymbolAddress((void**)&bH,   g_H);
    cudaGetSymbolAddress((void**)&bF1,  g_F1);
    cudaGetSymbolAddress((void**)&bF2,  g_F2);
    cudaGetSymbolAddress((void**)&bXh, g_Xt_h); cudaGetSymbolAddress((void**)&bXm, g_Xt_m);
    cudaGetSymbolAddress((void**)&bXl, g_Xt_l);
    cudaGetSymbolAddress((void**)&bHh, g_Ht_h); cudaGetSymbolAddress((void**)&bHm, g_Ht_m);
    cudaGetSymbolAddress((void**)&bHl, g_Ht_l);
    cudaGetSymbolAddress((void**)&bSpOt, g_SpOt);
    cudaGetSymbolAddress((void**)&bS2t,  g_S2t);
    cudaGetSymbolAddress((void**)&wqh, g_Wq_h); cudaGetSymbolAddress((void**)&wqm, g_Wq_m);
    cudaGetSymbolAddress((void**)&wql, g_Wq_l);
    cudaGetSymbolAddress((void**)&wph, g_Wp_h); cudaGetSymbolAddress((void**)&wpm, g_Wp_m);
    cudaGetSymbolAddress((void**)&wpl, g_Wp_l);
    cudaGetSymbolAddress((void**)&w1h, g_W1_h); cudaGetSymbolAddress((void**)&w1m, g_W1_m);
    cudaGetSymbolAddress((void**)&w1l, g_W1_l);
    cudaGetSymbolAddress((void**)&w2h, g_W2_h); cudaGetSymbolAddress((void**)&w2m, g_W2_m);
    cudaGetSymbolAddress((void**)&w2l, g_W2_l);

    const int SM6 = 73728;   // A 48KB + B 24KB
    const int SM1 = 57344;   // A 48KB + B 8KB
    cudaFuncSetAttribute(upconv_lif_kernel, cudaFuncAttributeMaxDynamicSharedMemorySize, 82080);
    cudaFuncSetAttribute(gemm_mma_kernel<256,3>,  cudaFuncAttributeMaxDynamicSharedMemorySize, SM6);
    cudaFuncSetAttribute(gemm_mma_kernel<256,1>,  cudaFuncAttributeMaxDynamicSharedMemorySize, SM1);
    cudaFuncSetAttribute(gemm_mma_kernel<1024,1>, cudaFuncAttributeMaxDynamicSharedMemorySize, SM1);

    prep_kernel<<<43, 256>>>(tim_up_w, tim_bn1);
    prep_w_kernel<<<3072, 256>>>(q_w, k_w, v_w, proj_w, fc1_w, fc2_w);

    // --- qkv (mma.sync tensor cores) -> TIM pipeline ---
    cvt_xt_kernel<<<dim3(8,8,40), 256>>>(x, bXh, bXm, bXl);
    gemm_mma_kernel<256,3><<<dim3(4,2,120), 256, SM6>>>(
        bXh, bXm, bXl, wqh, wqm, wql, q_bn, k_bn, v_bn, nullptr, bA, 256);
    upconv_lif_kernel<<<dim3(256,4,3), 256, 82080>>>(bA, bM);
    downconv_lif_kernel<<<dim3(256,4,3), 256>>>(bM, tim_dn_w, tim_bn2, bQKV);

    // --- attention + attn-LIF (binary bf16 transposed) ---
    attn_kernel<<<dim3(16,4,10), 256>>>(bQKV, bQKV + BR_STRIDE_A, bQKV + 2*BR_STRIDE_A, bO);
    lif_t_bf16_kernel<<<dim3(8,8,4), 256>>>(bO, bSpOt, 256, 0.5f);

    // --- proj (binary X, 3 products) + residual ---
    gemm_mma_kernel<256,1><<<dim3(4,2,40), 256, SM1>>>(
        bSpOt, nullptr, nullptr, wph, wpm, wpl, proj_bn, proj_bn, proj_bn, nullptr, bP, 256);
    lif_std_kernel<<<1024, 256>>>(bP, bH, x, 256, 1.0f);

    // --- mlp ---
    cvt_xt_kernel<<<dim3(8,8,40), 256>>>(bH, bHh, bHm, bHl);
    gemm_mma_kernel<256,3><<<dim3(4,8,40), 256, SM6>>>(
        bHh, bHm, bHl, w1h, w1m, w1l, fc1_bn, fc1_bn, fc1_bn, fc1_b, bF1, 1024);
    lif_t_bf16_kernel<<<dim3(32,8,4), 256>>>(bF1, bS2t, 1024, 1.0f);
    gemm_mma_kernel<1024,1><<<dim3(4,2,40), 256, SM1>>>(
        bS2t, nullptr, nullptr, w2h, w2m, w2l, fc2_bn, fc2_bn, fc2_bn, fc2_b, bF2, 256);
    lif_std_kernel<<<1024, 256>>>(bF2, out, bH, 256, 1.0f);
}

// round 14
// speedup vs baseline: 2.8128x; 1.0268x over previous
#include <cuda_runtime.h>
#include <cuda_bf16.h>
#include <cstdint>

#define TT 10
#define BB 4
#define CCH 256
#define NPIX 256
#define HIDN 1024
#define TRJ 40
#define EPSF 1e-5f

typedef unsigned long long u64;
typedef __nv_bfloat16 bf16;

#define FMA2(d,a,b)    asm("fma.rn.f32x2 %0, %1, %2, %0;" : "+l"(d) : "l"(a), "l"(b))
#define PACK2(d,lo,hi) asm("mov.b64 %0, {%1, %2};" : "=l"(d) : "f"(lo), "f"(hi))
#define UNPACK2(lo,hi,s) asm("mov.b64 {%0, %1}, %2;" : "=f"(lo), "=f"(hi) : "l"(s))

#define BR_STRIDE_A  2621440

// ---------------- mma.sync helpers (sm_80+ PTX, works on plain sm_103 target) ----------
__device__ __forceinline__ uint32_t smem_to_u32(const void* p) {
    uint32_t a;
    asm("{ .reg .u64 t; cvta.to.shared.u64 t, %1; cvt.u32.u64 %0, t; }" : "=r"(a) : "l"(p));
    return a;
}
#define LDSM4(r, addr) \
    asm volatile("ldmatrix.sync.aligned.m8n8.x4.shared.b16 {%0,%1,%2,%3}, [%4];" \
        : "=r"((r)[0]), "=r"((r)[1]), "=r"((r)[2]), "=r"((r)[3]) : "r"(addr))
#define MMA16816(c, a, b0v, b1v) \
    asm volatile("mma.sync.aligned.m16n8k16.row.col.f32.bf16.bf16.f32 " \
        "{%0,%1,%2,%3}, {%4,%5,%6,%7}, {%8,%9}, {%0,%1,%2,%3};" \
        : "+f"((c)[0]), "+f"((c)[1]), "+f"((c)[2]), "+f"((c)[3]) \
        : "r"((a)[0]), "r"((a)[1]), "r"((a)[2]), "r"((a)[3]), "r"(b0v), "r"(b1v))

// ---------------- scratch ----------------
__device__ float g_A  [3*TT*BB*CCH*NPIX];
__device__ u64   g_M  [3*BB*CCH*NPIX];
__device__ unsigned g_QKVb[3*TT*BB*CCH*8];   // spike bitmasks [br][(t*4+b)][c][w], bit=pixel
__device__ float g_O  [TT*BB*CCH*NPIX];
__device__ float g_P  [TT*BB*CCH*NPIX];
__device__ float g_H  [TT*BB*CCH*NPIX];
__device__ float g_F1 [TT*BB*HIDN*NPIX];
__device__ float g_F2 [TT*BB*CCH*NPIX];
__device__ float g_WupT[270*40];
__device__ float g_bn1s[40], g_bn1o[40];
// bf16 limbs
__device__ bf16 g_Wq_h[196608], g_Wq_m[196608], g_Wq_l[196608];
__device__ bf16 g_Wp_h[65536],  g_Wp_m[65536],  g_Wp_l[65536];
__device__ bf16 g_W1_h[262144], g_W1_m[262144], g_W1_l[262144];
__device__ bf16 g_W2_h[262144], g_W2_m[262144], g_W2_l[262144];
__device__ bf16 g_Xt_h[2621440], g_Xt_m[2621440], g_Xt_l[2621440];
__device__ bf16 g_Ht_h[2621440], g_Ht_m[2621440], g_Ht_l[2621440];
__device__ bf16 g_SpOt[2621440];     // binary, [g][n][256]
__device__ bf16 g_S2t[10485760];     // binary, [g][n][1024]

__device__ __forceinline__ void split3(float v, bf16& h, bf16& m, bf16& l) {
    h = __float2bfloat16(v);
    float r1 = v - __bfloat162float(h);
    m = __float2bfloat16(r1);
    l = __float2bfloat16(r1 - __bfloat162float(m));
}

// ---------------- prep ----------------
__global__ void prep_kernel(const float* __restrict__ up_w, const float* __restrict__ bn1) {
    for (int idx = blockIdx.x*blockDim.x + threadIdx.x; idx < 10800;
         idx += gridDim.x*blockDim.x) {
        int j = idx / 270, r = idx % 270;
        g_WupT[r*40 + j] = up_w[idx];
    }
    int i = blockIdx.x*blockDim.x + threadIdx.x;
    if (i < 40) {
        float gm = bn1[i], bt = bn1[40+i], mu = bn1[80+i], vr = bn1[120+i];
        float s = gm * rsqrtf(vr + EPSF);
        g_bn1s[i] = s; g_bn1o[i] = bt - mu*s;
    }
}

__global__ void prep_w_kernel(const float* __restrict__ q_w, const float* __restrict__ k_w,
                              const float* __restrict__ v_w, const float* __restrict__ proj_w,
                              const float* __restrict__ fc1_w, const float* __restrict__ fc2_w) {
    int i = blockIdx.x*256 + threadIdx.x;
    if (i >= 786432) return;
    float v; bf16 *dh, *dm, *dl; int o;
    if (i < 196608) {
        int br = i >> 16;
        const float* w = (br == 0) ? q_w : ((br == 1) ? k_w : v_w);
        v = w[i & 65535]; o = i; dh = g_Wq_h; dm = g_Wq_m; dl = g_Wq_l;
    } else if (i < 262144) {
        o = i - 196608; v = proj_w[o]; dh = g_Wp_h; dm = g_Wp_m; dl = g_Wp_l;
    } else if (i < 524288) {
        o = i - 262144; v = fc1_w[o]; dh = g_W1_h; dm = g_W1_m; dl = g_W1_l;
    } else {
        o = i - 524288; v = fc2_w[o]; dh = g_W2_h; dm = g_W2_m; dl = g_W2_l;
    }
    bf16 h, m, l; split3(v, h, m, l);
    dh[o] = h; dm[o] = m; dl[o] = l;
}

// float [g][256][256] -> transposed 3-limb bf16 [g][n][256]
__global__ void cvt_xt_kernel(const float* __restrict__ X, bf16* __restrict__ Xh,
                              bf16* __restrict__ Xm, bf16* __restrict__ Xl) {
    __shared__ float s[32][33];
    const int c0 = blockIdx.x*32, n0 = blockIdx.y*32, g = blockIdx.z;
    const int tid = threadIdx.x;
    #pragma unroll
    for (int it = 0; it < 4; it++) {
        int c = (tid>>5) + it*8;
        s[c][tid&31] = X[((size_t)g*256 + c0+c)*256 + n0 + (tid&31)];
    }
    __syncthreads();
    const int cc = tid & 31;
    #pragma unroll
    for (int it = 0; it < 4; it++) {
        int nn = (tid>>5) + it*8;
        bf16 h, m, l; split3(s[cc][nn], h, m, l);
        size_t o = ((size_t)g*256 + n0+nn)*256 + c0+cc;
        Xh[o] = h; Xm[o] = m; Xl[o] = l;
    }
}

// LIF over t + transpose to binary bf16 [g][n][C]
__global__ void lif_t_bf16_kernel(const float* __restrict__ in, bf16* __restrict__ out,
                                  int C, float vth) {
    __shared__ float s[10][32][33];
    const int c0 = blockIdx.x*32, n0 = blockIdx.y*32, b = blockIdx.z;
    const int tid = threadIdx.x;
    for (int t = 0; t < 10; t++)
        #pragma unroll
        for (int it = 0; it < 4; it++) {
            int c = (tid>>5) + it*8;
            s[t][c][tid&31] = in[((size_t)(t*4+b)*C + c0+c)*256 + n0 + (tid&31)];
        }
    __syncthreads();
    const int cc = tid & 31;
    #pragma unroll
    for (int pass = 0; pass < 4; pass++) {
        int nn = (tid>>5) + pass*8;
        float memv = 0.f;
        #pragma unroll
        for (int t = 0; t < 10; t++) {
            float x = s[t][cc][nn];
            memv += 0.5f*(x - memv);
            float sp = memv > vth ? 1.f : 0.f;
            out[((size_t)(t*4+b)*256 + n0+nn)*C + c0+cc] = __float2bfloat16(sp);
            if (sp > 0.f) memv = 0.f;
        }
    }
}

// ---------------- mma.sync GEMM + BN(+bias), limb-decomposed --------------------------
template<int CIN, int NB>
__global__ void __launch_bounds__(256, 3) gemm_mma_kernel(
        const bf16* __restrict__ Xh, const bf16* __restrict__ Xm, const bf16* __restrict__ Xl,
        const bf16* __restrict__ Wh, const bf16* __restrict__ Wm, const bf16* __restrict__ Wl,
        const float* __restrict__ B0, const float* __restrict__ B1, const float* __restrict__ B2,
        const float* __restrict__ bias, float* __restrict__ Y, int Cout) {
    extern __shared__ char dsm[];
    const int z = blockIdx.z, br = z/40, g = z - br*40;
    const int mo = blockIdx.y*128, no = blockIdx.x*64;
    const int tid = threadIdx.x, wid = tid>>5, lane = tid&31;
    const bf16* Wp[3] = {Wh + (size_t)br*Cout*CIN, Wm + (size_t)br*Cout*CIN,
                         Wl + (size_t)br*Cout*CIN};
    const bf16* Xp[3];
    Xp[0] = Xh + (size_t)g*256*CIN;
    Xp[1] = (NB > 1) ? Xm + (size_t)g*256*CIN : Xp[0];
    Xp[2] = (NB > 1) ? Xl + (size_t)g*256*CIN : Xp[0];

    float acc[8][4];
    #pragma unroll
    for (int j = 0; j < 8; j++)
        #pragma unroll
        for (int i = 0; i < 4; i++) acc[j][i] = 0.f;

    const uint32_t sbase = smem_to_u32(dsm);
    const int rowA = wid*16 + (lane & 7) + ((lane & 8) ? 8 : 0);
    const int h16A = (lane & 16) ? 16 : 0;
    const int axor = (rowA & 7)*16;
    const uint32_t aoff = sbase + rowA*128;
    const int rB = (lane & 7) + ((lane & 16) ? 8 : 0);
    const int h16B = (lane & 8) ? 16 : 0;
    const int bxor = (lane & 7)*16;
    const uint32_t boff = sbase + 49152 + rB*128;

    for (int ch = 0; ch < CIN/64; ch++) {
        #pragma unroll
        for (int l = 0; l < 3; l++) {
            #pragma unroll
            for (int it = 0; it < 4; it++) {
                int q = tid + it*256;
                int row = q >> 3, c16 = q & 7;
                uint4 v = *reinterpret_cast<const uint4*>(
                    &Wp[l][(size_t)(mo+row)*CIN + ch*64 + c16*8]);
                *reinterpret_cast<uint4*>(dsm + l*16384 + row*128 +
                                          ((c16*16) ^ ((row & 7)*16))) = v;
            }
        }
        #pragma unroll
        for (int l = 0; l < NB; l++) {
            #pragma unroll
            for (int it = 0; it < 2; it++) {
                int q = tid + it*256;
                int row = q >> 3, c16 = q & 7;
                uint4 v = *reinterpret_cast<const uint4*>(
                    &Xp[l][(size_t)(no+row)*CIN + ch*64 + c16*8]);
                *reinterpret_cast<uint4*>(dsm + 49152 + l*8192 + row*128 +
                                          ((c16*16) ^ ((row & 7)*16))) = v;
            }
        }
        __syncthreads();
        #pragma unroll
        for (int ks = 0; ks < 4; ks++) {
            uint32_t af[3][4];
            #pragma unroll
            for (int la = 0; la < 3; la++)
                LDSM4(af[la], aoff + la*16384 + ((ks*32 + h16A) ^ axor));
            #pragma unroll
            for (int j = 0; j < 4; j++) {
                #pragma unroll
                for (int lb = 0; lb < NB; lb++) {
                    uint32_t bf4[4];
                    LDSM4(bf4, boff + lb*8192 + j*2048 + ((ks*32 + h16B) ^ bxor));
                    const int lamax = (NB == 3) ? (3 - lb) : 3;
                    #pragma unroll
                    for (int la = 0; la < 3; la++) {
                        if (la < lamax) {
                            MMA16816(acc[2*j],   af[la], bf4[0], bf4[1]);
                            MMA16816(acc[2*j+1], af[la], bf4[2], bf4[3]);
                        }
                    }
                }
            }
        }
        __syncthreads();
    }
    const float* bnp = (br == 0) ? B0 : ((br == 1) ? B1 : B2);
    const int g4 = lane >> 2, tg = lane & 3;
    const int o0 = mo + wid*16 + g4, o1 = o0 + 8;
    float gm0 = bnp[o0], bt0 = bnp[Cout+o0], mu0 = bnp[2*Cout+o0], vr0 = bnp[3*Cout+o0];
    float s0 = gm0 * rsqrtf(vr0 + EPSF);
    float f0 = bt0 - mu0*s0 + (bias ? s0*bias[o0] : 0.f);
    float gm1 = bnp[o1], bt1 = bnp[Cout+o1], mu1 = bnp[2*Cout+o1], vr1 = bnp[3*Cout+o1];
    float s1 = gm1 * rsqrtf(vr1 + EPSF);
    float f1 = bt1 - mu1*s1 + (bias ? s1*bias[o1] : 0.f);
    float* Yb = Y + ((size_t)(br*40 + g)*Cout)*256;
    #pragma unroll
    for (int j = 0; j < 8; j++) {
        int col = no + j*8 + tg*2;
        float2 r0; r0.x = s0*acc[j][0] + f0; r0.y = s0*acc[j][1] + f0;
        *reinterpret_cast<float2*>(&Yb[(size_t)o0*256 + col]) = r0;
        float2 r1; r1.x = s1*acc[j][2] + f1; r1.y = s1*acc[j][3] + f1;
        *reinterpret_cast<float2*>(&Yb[(size_t)o1*256 + col]) = r1;
    }
}

// ---------------- TIM up-conv + bn1 + LIF1 -> 40-bit masks ------------------------------
__global__ void upconv_lif_kernel(const float* __restrict__ A, u64* __restrict__ M) {
    extern __shared__ __align__(16) float sm[];
    float* As  = sm;
    float* Wsm = sm + 9720;
    const int c = blockIdx.x, b = blockIdx.y, br = blockIdx.z;
    const float* Ab = A + (size_t)br * BR_STRIDE_A;
    const int tid = threadIdx.x;
    for (int i = tid; i < 10800; i += 256) Wsm[i] = g_WupT[i];
    for (int idx = tid; idx < 9720; idx += 256) {
        int t = idx / 972, q = idx % 972;
        int dc = q / 324, q2 = q % 324;
        int hh = q2 / 18, ww = q2 % 18;
        int cc = c - 1 + dc;
        float v = 0.f;
        if (cc >= 0 && cc < 256 && hh >= 1 && hh <= 16 && ww >= 1 && ww <= 16)
            v = Ab[((t*4 + b)*256 + cc)*256 + (hh-1)*16 + (ww-1)];
        As[idx] = v;
    }
    __syncthreads();
    const int h = tid >> 4, w = tid & 15;
    u64 acc[20];
    #pragma unroll
    for (int j = 0; j < 20; j++) acc[j] = 0ull;
    for (int t = 0; t < 10; t++) {
        const float* at = As + t*972 + h*18 + w;
        const u64* wt = reinterpret_cast<const u64*>(Wsm) + t*540;
        #pragma unroll
        for (int dc = 0; dc < 3; dc++)
            #pragma unroll
            for (int dh = 0; dh < 3; dh++)
                #pragma unroll
                for (int dw = 0; dw < 3; dw++) {
                    float a = at[dc*324 + dh*18 + dw];
                    u64 a2; PACK2(a2, a, a);
                    const ulonglong2* wp2 =
                        reinterpret_cast<const ulonglong2*>(wt + (dc*9 + dh*3 + dw)*20);
                    #pragma unroll
                    for (int j2 = 0; j2 < 10; j2++) {
                        ulonglong2 wv = wp2[j2];
                        FMA2(acc[2*j2  ], a2, wv.x);
                        FMA2(acc[2*j2+1], a2, wv.y);
                    }
                }
    }
    float av[40];
    #pragma unroll
    for (int p = 0; p < 20; p++) {
        float lo, hi; UNPACK2(lo, hi, acc[p]);
        av[2*p] = lo; av[2*p+1] = hi;
    }
    u64 mask = 0ull;
    #pragma unroll
    for (int q = 0; q < 4; q++) {
        float memv = 0.f;
        #pragma unroll
        for (int s = 0; s < 10; s++) {
            int j = 4*s + q;
            float x = g_bn1s[j]*av[j] + g_bn1o[j];
            memv += 0.5f*(x - memv);
            if (memv > 1.0f) { mask |= (1ull << j); memv = 0.f; }
        }
    }
    M[((size_t)(br*4 + b)*256 + c)*256 + tid] = mask;
}

// ---------------- TIM down-conv nibble-LUT + bn2 + LIF2 -> spike BITMASKS ---------------
// grid (c=256, b=4, br=3), 256 threads. Output: ballot bitmask per (t, c, warp).
__global__ void downconv_lif_kernel(const u64* __restrict__ Mg, const float* __restrict__ Wd_g,
                                    const float* __restrict__ bn2, unsigned* __restrict__ Bits) {
    const int c = blockIdx.x, b = blockIdx.y, br = blockIdx.z;
    const u64* Mb = Mg + (size_t)(br*4 + b)*65536;
    __shared__ __align__(16) u64 Ms[972];
    __shared__ float LUT[4320];
    __shared__ float s_sc[10], s_of[10];
    const int tid = threadIdx.x;
    for (int i = tid; i < 4320; i += 256) {
        int tap = i / 160, rem = i - tap*160;
        int t = rem >> 4, nib = rem & 15;
        float v = 0.f;
        if (nib & 1) v += Wd_g[t*108 +  0 + tap];
        if (nib & 2) v += Wd_g[t*108 + 27 + tap];
        if (nib & 4) v += Wd_g[t*108 + 54 + tap];
        if (nib & 8) v += Wd_g[t*108 + 81 + tap];
        LUT[i] = v;
    }
    if (tid < 10) {
        float gm = bn2[tid], bt = bn2[10+tid], mu = bn2[20+tid], vr = bn2[30+tid];
        float s = gm * rsqrtf(vr + EPSF);
        s_sc[tid] = s; s_of[tid] = bt - mu*s;
    }
    for (int i = tid; i < 972; i += 256) {
        int dc = i / 324, rem = i - dc*324;
        int hh = rem / 18, ww = rem - hh*18;
        int cc = c - 1 + dc;
        u64 m = 0ull;
        if (cc >= 0 && cc < 256 && hh >= 1 && hh <= 16 && ww >= 1 && ww <= 16)
            m = Mb[cc*256 + (hh-1)*16 + (ww-1)];
        Ms[i] = m;
    }
    __syncthreads();
    const int h = tid >> 4, w = tid & 15;
    float acc[10];
    #pragma unroll
    for (int t = 0; t < 10; t++) acc[t] = 0.f;
    #pragma unroll
    for (int dc = 0; dc < 3; dc++)
        #pragma unroll
        for (int dh = 0; dh < 3; dh++)
            #pragma unroll
            for (int dw = 0; dw < 3; dw++) {
                u64 m = Ms[dc*324 + (h+dh)*18 + (w+dw)];
                unsigned mlo = (unsigned)m, mhi = (unsigned)(m >> 32);
                const float* lt = LUT + (dc*9 + dh*3 + dw)*160;
                #pragma unroll
                for (int t = 0; t < 8; t++)
                    acc[t] += lt[t*16 + ((mlo >> (4*t)) & 15u)];
                acc[8] += lt[128 + (mhi & 15u)];
                acc[9] += lt[144 + ((mhi >> 4) & 15u)];
            }
    const int wid = tid >> 5, lane = tid & 31;
    float memv = 0.f;
    #pragma unroll
    for (int t = 0; t < 10; t++) {
        float x = s_sc[t]*acc[t] + s_of[t];
        memv += 0.5f*(x - memv);
        float sp = memv > 1.0f ? 1.f : 0.f;
        unsigned blt = __ballot_sync(0xffffffffu, sp > 0.f);
        if (lane == 0)
            Bits[br*81920 + ((t*4 + b)*256 + c)*8 + wid] = blt;
        if (sp > 0.f) memv = 0.f;
    }
}

// ---------------- attention via bit ops: G = K^T V by popc, o = Q G (exact) -------------
// grid (h=16, b=4, t=10), 256 threads. Bits layout [br][(t*4+b)][c][w].
__global__ void attn_kernel(const unsigned* __restrict__ Bits, float* __restrict__ Op) {
    const int hh = blockIdx.x, b = blockIdx.y, t = blockIdx.z;
    __shared__ unsigned Qsb[16][8], Ksb[16][8], Vsb[16][8];
    __shared__ __align__(16) float Gs[16][16];
    const int tid = threadIdx.x;
    const int gbase = ((t*4 + b)*256 + hh*16)*8;
    if (tid < 128) {
        int d = tid >> 3, w = tid & 7;
        Qsb[d][w] = Bits[gbase + d*8 + w];
        Ksb[d][w] = Bits[81920 + gbase + d*8 + w];
    } else {
        int r = tid - 128;
        int d = r >> 3, w = r & 7;
        Vsb[d][w] = Bits[163840 + gbase + d*8 + w];
    }
    __syncthreads();
    {   // G[d1][d2] = sum_m K[m,d1]*V[m,d2] via popc
        int d1 = tid >> 4, d2 = tid & 15;
        unsigned s = 0;
        #pragma unroll
        for (int w = 0; w < 8; w++)
            s += __popc(Ksb[d1][w] & Vsb[d2][w]);
        Gs[d1][d2] = (float)s;
    }
    __syncthreads();
    // o[n][d2] = sum_{d1: Q[d1,n]} G[d1][d2]
    const int n = tid;
    const int word = n >> 5;
    const unsigned bit = 1u << (n & 31);
    u64 one2; PACK2(one2, 1.0f, 1.0f);
    u64 acc2[8];
    #pragma unroll
    for (int i = 0; i < 8; i++) acc2[i] = 0ull;
    #pragma unroll
    for (int d1 = 0; d1 < 16; d1++) {
        if (Qsb[d1][word] & bit) {
            const u64* gp = reinterpret_cast<const u64*>(&Gs[d1][0]);
            #pragma unroll
            for (int i = 0; i < 8; i++) FMA2(acc2[i], one2, gp[i]);
        }
    }
    const int base = (t*4 + b)*65536 + hh*4096;
    #pragma unroll
    for (int i = 0; i < 8; i++) {
        float lo, hi; UNPACK2(lo, hi, acc2[i]);
        Op[base + (2*i  )*256 + n] = 0.25f*lo;
        Op[base + (2*i+1)*256 + n] = 0.25f*hi;
    }
}

// ---------------- float LIF over t ------------------------------------------------------
__global__ void lif_std_kernel(const float* __restrict__ in, float* __restrict__ out,
                               const float* __restrict__ res, int Cch, float vth) {
    int idx = blockIdx.x*256 + threadIdx.x;
    int per_b = Cch*256;
    int b = idx / per_b, cn = idx - b*per_b;
    float mem = 0.f;
    #pragma unroll
    for (int t = 0; t < 10; t++) {
        int off = (t*4 + b)*per_b + cn;
        float x = in[off];
        mem += 0.5f*(x - mem);
        float sp = mem > vth ? 1.f : 0.f;
        out[off] = res ? res[off] + sp : sp;
        if (sp > 0.f) mem = 0.f;
    }
}

// ---------------- launch ----------------
extern "C" void kernel_launch(void* const* d_in, const int* in_sizes, int n_in,
                              void* d_out, int out_size) {
    const float* x        = (const float*)d_in[0];
    const float* q_w      = (const float*)d_in[1];
    const float* q_bn     = (const float*)d_in[2];
    const float* k_w      = (const float*)d_in[3];
    const float* k_bn     = (const float*)d_in[4];
    const float* v_w      = (const float*)d_in[5];
    const float* v_bn     = (const float*)d_in[6];
    const float* proj_w   = (const float*)d_in[7];
    const float* proj_bn  = (const float*)d_in[8];
    const float* tim_up_w = (const float*)d_in[9];
    const float* tim_bn1  = (const float*)d_in[10];
    const float* tim_dn_w = (const float*)d_in[11];
    const float* tim_bn2  = (const float*)d_in[12];
    const float* fc1_w    = (const float*)d_in[13];
    const float* fc1_b    = (const float*)d_in[14];
    const float* fc1_bn   = (const float*)d_in[15];
    const float* fc2_w    = (const float*)d_in[16];
    const float* fc2_b    = (const float*)d_in[17];
    const float* fc2_bn   = (const float*)d_in[18];
    float* out = (float*)d_out;

    float *bA,*bO,*bP,*bH,*bF1,*bF2;
    u64 *bM;
    unsigned *bQKVb;
    bf16 *bXh,*bXm,*bXl,*bHh,*bHm,*bHl,*bSpOt,*bS2t;
    bf16 *wqh,*wqm,*wql,*wph,*wpm,*wpl,*w1h,*w1m,*w1l,*w2h,*w2m,*w2l;
    cudaGetSymbolAddress((void**)&bA,    g_A);
    cudaGetSymbolAddress((void**)&bM,    g_M);
    cudaGetSymbolAddress((void**)&bQKVb, g_QKVb);
    cudaGetSymbolAddress((void**)&bO,    g_O);
    cudaGetSymbolAddress((void**)&bP,    g_P);
    cudaGetSymbolAddress((void**)&bH,    g_H);
    cudaGetSymbolAddress((void**)&bF1,   g_F1);
    cudaGetSymbolAddress((void**)&bF2,   g_F2);
    cudaGetSymbolAddress((void**)&bXh, g_Xt_h); cudaGetSymbolAddress((void**)&bXm, g_Xt_m);
    cudaGetSymbolAddress((void**)&bXl, g_Xt_l);
    cudaGetSymbolAddress((void**)&bHh, g_Ht_h); cudaGetSymbolAddress((void**)&bHm, g_Ht_m);
    cudaGetSymbolAddress((void**)&bHl, g_Ht_l);
    cudaGetSymbolAddress((void**)&bSpOt, g_SpOt);
    cudaGetSymbolAddress((void**)&bS2t,  g_S2t);
    cudaGetSymbolAddress((void**)&wqh, g_Wq_h); cudaGetSymbolAddress((void**)&wqm, g_Wq_m);
    cudaGetSymbolAddress((void**)&wql, g_Wq_l);
    cudaGetSymbolAddress((void**)&wph, g_Wp_h); cudaGetSymbolAddress((void**)&wpm, g_Wp_m);
    cudaGetSymbolAddress((void**)&wpl, g_Wp_l);
    cudaGetSymbolAddress((void**)&w1h, g_W1_h); cudaGetSymbolAddress((void**)&w1m, g_W1_m);
    cudaGetSymbolAddress((void**)&w1l, g_W1_l);
    cudaGetSymbolAddress((void**)&w2h, g_W2_h); cudaGetSymbolAddress((void**)&w2m, g_W2_m);
    cudaGetSymbolAddress((void**)&w2l, g_W2_l);

    const int SM6 = 73728;   // A 48KB + B 24KB
    const int SM1 = 57344;   // A 48KB + B 8KB
    cudaFuncSetAttribute(upconv_lif_kernel, cudaFuncAttributeMaxDynamicSharedMemorySize, 82080);
    cudaFuncSetAttribute(gemm_mma_kernel<256,3>,  cudaFuncAttributeMaxDynamicSharedMemorySize, SM6);
    cudaFuncSetAttribute(gemm_mma_kernel<256,1>,  cudaFuncAttributeMaxDynamicSharedMemorySize, SM1);
    cudaFuncSetAttribute(gemm_mma_kernel<1024,1>, cudaFuncAttributeMaxDynamicSharedMemorySize, SM1);

    prep_kernel<<<43, 256>>>(tim_up_w, tim_bn1);
    prep_w_kernel<<<3072, 256>>>(q_w, k_w, v_w, proj_w, fc1_w, fc2_w);

    // --- qkv (mma.sync tensor cores) -> TIM pipeline -> spike bitmasks ---
    cvt_xt_kernel<<<dim3(8,8,40), 256>>>(x, bXh, bXm, bXl);
    gemm_mma_kernel<256,3><<<dim3(4,2,120), 256, SM6>>>(
        bXh, bXm, bXl, wqh, wqm, wql, q_bn, k_bn, v_bn, nullptr, bA, 256);
    upconv_lif_kernel<<<dim3(256,4,3), 256, 82080>>>(bA, bM);
    downconv_lif_kernel<<<dim3(256,4,3), 256>>>(bM, tim_dn_w, tim_bn2, bQKVb);

    // --- attention (popc, exact) + attn-LIF (binary bf16 transposed) ---
    attn_kernel<<<dim3(16,4,10), 256>>>(bQKVb, bO);
    lif_t_bf16_kernel<<<dim3(8,8,4), 256>>>(bO, bSpOt, 256, 0.5f);

    // --- proj (binary X, 3 products) + residual ---
    gemm_mma_kernel<256,1><<<dim3(4,2,40), 256, SM1>>>(
        bSpOt, nullptr, nullptr, wph, wpm, wpl, proj_bn, proj_bn, proj_bn, nullptr, bP, 256);
    lif_std_kernel<<<1024, 256>>>(bP, bH, x, 256, 1.0f);

    // --- mlp ---
    cvt_xt_kernel<<<dim3(8,8,40), 256>>>(bH, bHh, bHm, bHl);
    gemm_mma_kernel<256,3><<<dim3(4,8,40), 256, SM6>>>(
        bHh, bHm, bHl, w1h, w1m, w1l, fc1_bn, fc1_bn, fc1_bn, fc1_b, bF1, 1024);
    lif_t_bf16_kernel<<<dim3(32,8,4), 256>>>(bF1, bS2t, 1024, 1.0f);
    gemm_mma_kernel<1024,1><<<dim3(4,2,40), 256, SM1>>>(
        bS2t, nullptr, nullptr, w2h, w2m, w2l, fc2_bn, fc2_bn, fc2_bn, fc2_b, bF2, 256);
    lif_std_kernel<<<1024, 256>>>(bF2, out, bH, 256, 1.0f);
}